// round 1
// baseline (speedup 1.0000x reference)
#include <cuda_runtime.h>
#include <cstdint>

#define NMAX 50000
#define EMAX 800000
#define D 128

// ---------------- device scratch (no allocations allowed) ----------------
__device__ int   g_cnt[NMAX];
__device__ int   g_off[NMAX + 1];
__device__ int   g_cur[NMAX];
__device__ int   g_srcs[EMAX];
__device__ float g_attr[EMAX];
__device__ float g_h[3][NMAX * D];   // h1, h2, h3
__device__ float g_tmp[NMAX * D];
__device__ float g_mid[NMAX * D];

// ---------------- preprocessing: CSR by target via counting sort ----------------
__global__ void k_zero(int n) {
    int i = blockIdx.x * blockDim.x + threadIdx.x;
    if (i < n) g_cnt[i] = 0;
}

__global__ void k_hist(const int* __restrict__ tgt, int E) {
    int i = blockIdx.x * blockDim.x + threadIdx.x;
    if (i < E) atomicAdd(&g_cnt[tgt[i]], 1);
}

// single-block scan over n counts -> offsets + cursor init
__global__ void k_scan(int n) {
    __shared__ int sh[1024];
    __shared__ int carry;
    if (threadIdx.x == 0) { carry = 0; g_off[0] = 0; }
    __syncthreads();
    for (int base = 0; base < n; base += 1024) {
        int i = base + (int)threadIdx.x;
        int v = (i < n) ? g_cnt[i] : 0;
        sh[threadIdx.x] = v;
        __syncthreads();
        // Hillis-Steele inclusive scan
        #pragma unroll
        for (int d = 1; d < 1024; d <<= 1) {
            int t = (threadIdx.x >= (unsigned)d) ? sh[threadIdx.x - d] : 0;
            __syncthreads();
            sh[threadIdx.x] += t;
            __syncthreads();
        }
        int inc = sh[threadIdx.x];
        if (i < n) {
            g_off[i + 1] = carry + inc;
            g_cur[i]     = carry + inc - v;   // exclusive
        }
        __syncthreads();
        if (threadIdx.x == 1023) carry += sh[1023];
        __syncthreads();
    }
}

__global__ void k_scatter(const int* __restrict__ src, const int* __restrict__ tgt,
                          const float* __restrict__ ea, int E) {
    int i = blockIdx.x * blockDim.x + threadIdx.x;
    if (i < E) {
        int p = atomicAdd(&g_cur[tgt[i]], 1);
        g_srcs[p] = src[i];
        g_attr[p] = ea[i];
    }
}

// ---------------- aggregation: one warp per node ----------------
// out[n] = (sum_{e in N(n)} relu(h[src_e] + a_e*lw + lb)) / deg + (1+eps)*h[n]
__global__ void k_agg(const float* __restrict__ h,
                      const float* __restrict__ lw, const float* __restrict__ lb,
                      const float* __restrict__ eps, int l,
                      float* __restrict__ out, int n) {
    int warp = (blockIdx.x * blockDim.x + threadIdx.x) >> 5;
    int lane = threadIdx.x & 31;
    if (warp >= n) return;
    int s0 = g_off[warp], s1 = g_off[warp + 1];
    float4 lw4 = *(const float4*)(lw + lane * 4);
    float4 lb4 = *(const float4*)(lb + lane * 4);
    float4 acc = make_float4(0.f, 0.f, 0.f, 0.f);
    #pragma unroll 4
    for (int e = s0; e < s1; ++e) {
        int   s = g_srcs[e];
        float a = g_attr[e];
        float4 hv = *(const float4*)(h + (size_t)s * D + lane * 4);
        acc.x += fmaxf(fmaf(a, lw4.x, lb4.x) + hv.x, 0.f);
        acc.y += fmaxf(fmaf(a, lw4.y, lb4.y) + hv.y, 0.f);
        acc.z += fmaxf(fmaf(a, lw4.z, lb4.z) + hv.z, 0.f);
        acc.w += fmaxf(fmaf(a, lw4.w, lb4.w) + hv.w, 0.f);
    }
    float inv = 1.f / (float)(s1 - s0);
    float g   = 1.f + eps[l];
    float4 hn = *(const float4*)(h + (size_t)warp * D + lane * 4);
    float4 o;
    o.x = acc.x * inv + g * hn.x;
    o.y = acc.y * inv + g * hn.y;
    o.z = acc.z * inv + g * hn.z;
    o.w = acc.w * inv + g * hn.w;
    *(float4*)(out + (size_t)warp * D + lane * 4) = o;
}

// ---------------- GEMM: C[M,128] = concat(A0..A{NCHUNK-1})[M, NCHUNK*128] @ W + bias ----------------
// Tile: 64 rows x 128 cols per 256-thread block, BK=16.
template <int NCHUNK, bool RELU>
__global__ void __launch_bounds__(256) k_gemm(
    const float* __restrict__ A0, const float* __restrict__ A1,
    const float* __restrict__ A2, const float* __restrict__ A3,
    const float* __restrict__ W, const float* __restrict__ bias,
    float* __restrict__ C, int M)
{
    __shared__ float As[16][68];     // [k][row], pad 68 -> 16B aligned rows, low conflicts
    __shared__ float Ws[16][128];    // [k][col]

    const int tid = threadIdx.x;
    const int tx  = tid & 31;        // lane -> 4 output cols
    const int ty  = tid >> 5;        // warp -> 8 output rows
    const int br  = blockIdx.x * 64;

    float acc[8][4];
    #pragma unroll
    for (int i = 0; i < 8; ++i)
        #pragma unroll
        for (int j = 0; j < 4; ++j) acc[i][j] = 0.f;

    const int r   = tid >> 2;          // A-tile row this thread loads
    const int kq  = (tid & 3) * 4;     // A-tile k offset (float4)
    const int row = br + r;

    for (int kt = 0; kt < NCHUNK * 8; ++kt) {
        const float* Asrc;
        if (NCHUNK == 1) Asrc = A0;
        else {
            int c = kt >> 3;
            Asrc = (c == 0) ? A0 : (c == 1) ? A1 : (c == 2) ? A2 : A3;
        }
        int kb = (kt & 7) * 16;

        float4 av = make_float4(0.f, 0.f, 0.f, 0.f);
        if (row < M) av = *(const float4*)(Asrc + (size_t)row * D + kb + kq);

        float4 wv[2];
        #pragma unroll
        for (int p = 0; p < 2; ++p) {
            int f = tid + 256 * p;
            int kk = f >> 5, c4 = f & 31;
            wv[p] = *(const float4*)(W + (size_t)(kt * 16 + kk) * 128 + c4 * 4);
        }

        __syncthreads();
        As[kq + 0][r] = av.x;
        As[kq + 1][r] = av.y;
        As[kq + 2][r] = av.z;
        As[kq + 3][r] = av.w;
        #pragma unroll
        for (int p = 0; p < 2; ++p) {
            int f = tid + 256 * p;
            int kk = f >> 5, c4 = f & 31;
            *(float4*)&Ws[kk][c4 * 4] = wv[p];
        }
        __syncthreads();

        #pragma unroll
        for (int kk = 0; kk < 16; ++kk) {
            float4 alo = *(const float4*)&As[kk][ty * 8];
            float4 ahi = *(const float4*)&As[kk][ty * 8 + 4];
            float4 w4  = *(const float4*)&Ws[kk][tx * 4];
            float a[8] = {alo.x, alo.y, alo.z, alo.w, ahi.x, ahi.y, ahi.z, ahi.w};
            float w[4] = {w4.x, w4.y, w4.z, w4.w};
            #pragma unroll
            for (int i = 0; i < 8; ++i)
                #pragma unroll
                for (int j = 0; j < 4; ++j)
                    acc[i][j] = fmaf(a[i], w[j], acc[i][j]);
        }
    }

    float4 b4 = *(const float4*)(bias + tx * 4);
    #pragma unroll
    for (int i = 0; i < 8; ++i) {
        int rr = br + ty * 8 + i;
        if (rr < M) {
            float4 o;
            o.x = acc[i][0] + b4.x;
            o.y = acc[i][1] + b4.y;
            o.z = acc[i][2] + b4.z;
            o.w = acc[i][3] + b4.w;
            if (RELU) {
                o.x = fmaxf(o.x, 0.f); o.y = fmaxf(o.y, 0.f);
                o.z = fmaxf(o.z, 0.f); o.w = fmaxf(o.w, 0.f);
            }
            *(float4*)(C + (size_t)rr * D + tx * 4) = o;
        }
    }
}

// ---------------- launcher ----------------
extern "C" void kernel_launch(void* const* d_in, const int* in_sizes, int n_in,
                              void* d_out, int out_size) {
    const float* x   = (const float*)d_in[0];
    const int*   ei  = (const int*)  d_in[1];   // [2, E]: row0 = src, row1 = tgt
    const float* ea  = (const float*)d_in[2];   // [E, 1]
    const float* lw  = (const float*)d_in[3];   // [3, 1, 128]
    const float* lb  = (const float*)d_in[4];   // [3, 128]
    const float* eps = (const float*)d_in[5];   // [3]
    const float* w1  = (const float*)d_in[6];   // [3, 128, 128]
    const float* b1  = (const float*)d_in[7];
    const float* w2  = (const float*)d_in[8];
    const float* b2  = (const float*)d_in[9];
    const float* fw  = (const float*)d_in[10];  // [512, 128]
    const float* fb  = (const float*)d_in[11];  // [128]
    float* out = (float*)d_out;

    const int N = in_sizes[0] / D;
    const int E = in_sizes[2];

    float *hbuf, *tmp, *mid;
    cudaGetSymbolAddress((void**)&hbuf, g_h);
    cudaGetSymbolAddress((void**)&tmp,  g_tmp);
    cudaGetSymbolAddress((void**)&mid,  g_mid);

    // CSR build (once per call)
    k_zero<<<(N + 255) / 256, 256>>>(N);
    k_hist<<<(E + 255) / 256, 256>>>(ei + E, E);
    k_scan<<<1, 1024>>>(N);
    k_scatter<<<(E + 255) / 256, 256>>>(ei, ei + E, ea, E);

    const int gb = (N + 63) / 64;
    const float* h = x;
    for (int l = 0; l < 3; ++l) {
        float* hl = hbuf + (size_t)l * NMAX * D;
        k_agg<<<(N + 7) / 8, 256>>>(h, lw + l * D, lb + l * D, eps, l, tmp, N);
        k_gemm<1, true ><<<gb, 256>>>(tmp, nullptr, nullptr, nullptr,
                                      w1 + (size_t)l * D * D, b1 + l * D, mid, N);
        k_gemm<1, false><<<gb, 256>>>(mid, nullptr, nullptr, nullptr,
                                      w2 + (size_t)l * D * D, b2 + l * D, hl, N);
        h = hl;
    }

    // final: [x | h1 | h2 | h3] @ fw + fb
    k_gemm<4, false><<<gb, 256>>>(x, hbuf, hbuf + (size_t)NMAX * D,
                                  hbuf + (size_t)2 * NMAX * D, fw, fb, out, N);
}

// round 2
// speedup vs baseline: 1.1911x; 1.1911x over previous
#include <cuda_runtime.h>
#include <cstdint>

#define NMAX 50000
#define EMAX 800000
#define D 128

// ---------------- device scratch (no allocations allowed) ----------------
__device__ int   g_cnt[NMAX];
__device__ int   g_off[NMAX + 1];
__device__ int   g_cur[NMAX];
__device__ int   g_srcs[EMAX];
__device__ float g_attr[EMAX];
__device__ float g_h[3][NMAX * D];   // h1, h2, h3
__device__ float g_tmp[NMAX * D];
__device__ float g_mid[NMAX * D];

// ---------------- packed f32x2 helpers (Blackwell fma.rn.f32x2) ----------------
__device__ __forceinline__ unsigned long long pack2(float v) {
    unsigned long long r;
    asm("mov.b64 %0, {%1, %1};" : "=l"(r) : "f"(v));
    return r;
}
__device__ __forceinline__ void ffma2(unsigned long long& d,
                                      unsigned long long a,
                                      unsigned long long b) {
    asm("fma.rn.f32x2 %0, %1, %2, %0;" : "+l"(d) : "l"(a), "l"(b));
}
__device__ __forceinline__ void unpack2(unsigned long long v, float& lo, float& hi) {
    asm("mov.b64 {%0, %1}, %2;" : "=f"(lo), "=f"(hi) : "l"(v));
}

// ---------------- preprocessing: CSR by target via counting sort ----------------
__global__ void k_zero(int n) {
    int i = blockIdx.x * blockDim.x + threadIdx.x;
    if (i < n) g_cnt[i] = 0;
}

__global__ void k_hist(const int* __restrict__ tgt, int E) {
    int i = blockIdx.x * blockDim.x + threadIdx.x;
    if (i < E) atomicAdd(&g_cnt[tgt[i]], 1);
}

// single-block scan over n counts -> offsets + cursor init (shfl warp scan)
__global__ void k_scan(int n) {
    __shared__ int wsum[32];
    __shared__ int carry;
    const int lane = threadIdx.x & 31;
    const int wid  = threadIdx.x >> 5;
    if (threadIdx.x == 0) { carry = 0; g_off[0] = 0; }
    __syncthreads();
    for (int base = 0; base < n; base += 1024) {
        int i = base + (int)threadIdx.x;
        int v = (i < n) ? g_cnt[i] : 0;
        // inclusive warp scan
        int s = v;
        #pragma unroll
        for (int d = 1; d < 32; d <<= 1) {
            int t = __shfl_up_sync(0xFFFFFFFFu, s, d);
            if (lane >= d) s += t;
        }
        if (lane == 31) wsum[wid] = s;
        __syncthreads();
        if (wid == 0) {
            int ws = wsum[lane];
            #pragma unroll
            for (int d = 1; d < 32; d <<= 1) {
                int t = __shfl_up_sync(0xFFFFFFFFu, ws, d);
                if (lane >= d) ws += t;
            }
            wsum[lane] = ws;
        }
        __syncthreads();
        int incl = s + (wid ? wsum[wid - 1] : 0) + carry;
        if (i < n) {
            g_off[i + 1] = incl;
            g_cur[i]     = incl - v;   // exclusive
        }
        __syncthreads();
        if (threadIdx.x == 1023) carry = incl;
        __syncthreads();
    }
}

__global__ void k_scatter(const int* __restrict__ src, const int* __restrict__ tgt,
                          const float* __restrict__ ea, int E) {
    int i = blockIdx.x * blockDim.x + threadIdx.x;
    if (i < E) {
        int p = atomicAdd(&g_cur[tgt[i]], 1);
        g_srcs[p] = src[i];
        g_attr[p] = ea[i];
    }
}

// ---------------- aggregation: one warp per node ----------------
__global__ void k_agg(const float* __restrict__ h,
                      const float* __restrict__ lw, const float* __restrict__ lb,
                      const float* __restrict__ eps, int l,
                      float* __restrict__ out, int n) {
    int warp = (blockIdx.x * blockDim.x + threadIdx.x) >> 5;
    int lane = threadIdx.x & 31;
    if (warp >= n) return;
    int s0 = g_off[warp], s1 = g_off[warp + 1];
    float4 lw4 = *(const float4*)(lw + lane * 4);
    float4 lb4 = *(const float4*)(lb + lane * 4);
    float4 acc = make_float4(0.f, 0.f, 0.f, 0.f);
    #pragma unroll 4
    for (int e = s0; e < s1; ++e) {
        int   s = g_srcs[e];
        float a = g_attr[e];
        float4 hv = *(const float4*)(h + (size_t)s * D + lane * 4);
        acc.x += fmaxf(fmaf(a, lw4.x, lb4.x) + hv.x, 0.f);
        acc.y += fmaxf(fmaf(a, lw4.y, lb4.y) + hv.y, 0.f);
        acc.z += fmaxf(fmaf(a, lw4.z, lb4.z) + hv.z, 0.f);
        acc.w += fmaxf(fmaf(a, lw4.w, lb4.w) + hv.w, 0.f);
    }
    float inv = 1.f / (float)(s1 - s0);
    float g   = 1.f + eps[l];
    float4 hn = *(const float4*)(h + (size_t)warp * D + lane * 4);
    float4 o;
    o.x = acc.x * inv + g * hn.x;
    o.y = acc.y * inv + g * hn.y;
    o.z = acc.z * inv + g * hn.z;
    o.w = acc.w * inv + g * hn.w;
    *(float4*)(out + (size_t)warp * D + lane * 4) = o;
}

// ---------------- GEMM: C[M,128] = concat(A0..A{NCHUNK-1})[M, NCHUNK*128] @ W + bias ----
// Tile: 64 rows x 128 cols per 256-thread block, BK=16.
// Inner product uses packed fma.rn.f32x2: 16 FFMA2/k-step/thread (32 FMA).
template <int NCHUNK, bool RELU>
__global__ void __launch_bounds__(256) k_gemm(
    const float* __restrict__ A0, const float* __restrict__ A1,
    const float* __restrict__ A2, const float* __restrict__ A3,
    const float* __restrict__ W, const float* __restrict__ bias,
    float* __restrict__ C, int M)
{
    __shared__ float As[16][68];     // [k][row], stride 68 -> 16B-aligned rows
    __shared__ float Ws[16][128];    // [k][col]

    const int tid = threadIdx.x;
    const int tx  = tid & 31;        // lane -> 4 output cols
    const int ty  = tid >> 5;        // warp -> 8 output rows (4 packed pairs)
    const int br  = blockIdx.x * 64;

    unsigned long long acc2[4][4];   // [row-pair][col]
    #pragma unroll
    for (int p = 0; p < 4; ++p)
        #pragma unroll
        for (int j = 0; j < 4; ++j) acc2[p][j] = 0ull;

    const int r   = tid >> 2;          // A-tile row this thread loads
    const int kq  = (tid & 3) * 4;     // A-tile k offset (float4)
    const int row = br + r;

    for (int kt = 0; kt < NCHUNK * 8; ++kt) {
        const float* Asrc;
        if (NCHUNK == 1) Asrc = A0;
        else {
            int c = kt >> 3;
            Asrc = (c == 0) ? A0 : (c == 1) ? A1 : (c == 2) ? A2 : A3;
        }
        int kb = (kt & 7) * 16;

        float4 av = make_float4(0.f, 0.f, 0.f, 0.f);
        if (row < M) av = *(const float4*)(Asrc + (size_t)row * D + kb + kq);

        float4 wv[2];
        #pragma unroll
        for (int p = 0; p < 2; ++p) {
            int f = tid + 256 * p;
            int kk = f >> 5, c4 = f & 31;
            wv[p] = *(const float4*)(W + (size_t)(kt * 16 + kk) * 128 + c4 * 4);
        }

        __syncthreads();
        As[kq + 0][r] = av.x;
        As[kq + 1][r] = av.y;
        As[kq + 2][r] = av.z;
        As[kq + 3][r] = av.w;
        #pragma unroll
        for (int p = 0; p < 2; ++p) {
            int f = tid + 256 * p;
            int kk = f >> 5, c4 = f & 31;
            *(float4*)&Ws[kk][c4 * 4] = wv[p];
        }
        __syncthreads();

        #pragma unroll
        for (int kk = 0; kk < 16; ++kk) {
            unsigned long long a2[4];
            #pragma unroll
            for (int p = 0; p < 4; ++p)
                a2[p] = *(const unsigned long long*)&As[kk][ty * 8 + 2 * p]; // LDS.64 bcast
            float4 w4 = *(const float4*)&Ws[kk][tx * 4];
            unsigned long long wb[4] = {pack2(w4.x), pack2(w4.y), pack2(w4.z), pack2(w4.w)};
            #pragma unroll
            for (int p = 0; p < 4; ++p)
                #pragma unroll
                for (int j = 0; j < 4; ++j)
                    ffma2(acc2[p][j], a2[p], wb[j]);
        }
    }

    float4 b4 = *(const float4*)(bias + tx * 4);
    #pragma unroll
    for (int p = 0; p < 4; ++p) {
        float lo[4], hi[4];
        #pragma unroll
        for (int j = 0; j < 4; ++j) unpack2(acc2[p][j], lo[j], hi[j]);
        int r0 = br + ty * 8 + 2 * p;
        if (r0 < M) {
            float4 o;
            o.x = lo[0] + b4.x; o.y = lo[1] + b4.y;
            o.z = lo[2] + b4.z; o.w = lo[3] + b4.w;
            if (RELU) {
                o.x = fmaxf(o.x, 0.f); o.y = fmaxf(o.y, 0.f);
                o.z = fmaxf(o.z, 0.f); o.w = fmaxf(o.w, 0.f);
            }
            *(float4*)(C + (size_t)r0 * D + tx * 4) = o;
        }
        if (r0 + 1 < M) {
            float4 o;
            o.x = hi[0] + b4.x; o.y = hi[1] + b4.y;
            o.z = hi[2] + b4.z; o.w = hi[3] + b4.w;
            if (RELU) {
                o.x = fmaxf(o.x, 0.f); o.y = fmaxf(o.y, 0.f);
                o.z = fmaxf(o.z, 0.f); o.w = fmaxf(o.w, 0.f);
            }
            *(float4*)(C + (size_t)(r0 + 1) * D + tx * 4) = o;
        }
    }
}

// ---------------- launcher ----------------
extern "C" void kernel_launch(void* const* d_in, const int* in_sizes, int n_in,
                              void* d_out, int out_size) {
    const float* x   = (const float*)d_in[0];
    const int*   ei  = (const int*)  d_in[1];   // [2, E]: row0 = src, row1 = tgt
    const float* ea  = (const float*)d_in[2];   // [E, 1]
    const float* lw  = (const float*)d_in[3];   // [3, 1, 128]
    const float* lb  = (const float*)d_in[4];   // [3, 128]
    const float* eps = (const float*)d_in[5];   // [3]
    const float* w1  = (const float*)d_in[6];   // [3, 128, 128]
    const float* b1  = (const float*)d_in[7];
    const float* w2  = (const float*)d_in[8];
    const float* b2  = (const float*)d_in[9];
    const float* fw  = (const float*)d_in[10];  // [512, 128]
    const float* fb  = (const float*)d_in[11];  // [128]
    float* out = (float*)d_out;

    const int N = in_sizes[0] / D;
    const int E = in_sizes[2];

    float *hbuf, *tmp, *mid;
    cudaGetSymbolAddress((void**)&hbuf, g_h);
    cudaGetSymbolAddress((void**)&tmp,  g_tmp);
    cudaGetSymbolAddress((void**)&mid,  g_mid);

    // CSR build (once per call)
    k_zero<<<(N + 255) / 256, 256>>>(N);
    k_hist<<<(E + 255) / 256, 256>>>(ei + E, E);
    k_scan<<<1, 1024>>>(N);
    k_scatter<<<(E + 255) / 256, 256>>>(ei, ei + E, ea, E);

    const int gb = (N + 63) / 64;
    const float* h = x;
    for (int l = 0; l < 3; ++l) {
        float* hl = hbuf + (size_t)l * NMAX * D;
        k_agg<<<(N + 7) / 8, 256>>>(h, lw + l * D, lb + l * D, eps, l, tmp, N);
        k_gemm<1, true ><<<gb, 256>>>(tmp, nullptr, nullptr, nullptr,
                                      w1 + (size_t)l * D * D, b1 + l * D, mid, N);
        k_gemm<1, false><<<gb, 256>>>(mid, nullptr, nullptr, nullptr,
                                      w2 + (size_t)l * D * D, b2 + l * D, hl, N);
        h = hl;
    }

    // final: [x | h1 | h2 | h3] @ fw + fb
    k_gemm<4, false><<<gb, 256>>>(x, hbuf, hbuf + (size_t)NMAX * D,
                                  hbuf + (size_t)2 * NMAX * D, fw, fb, out, N);
}

// round 4
// speedup vs baseline: 1.5139x; 1.2711x over previous
#include <cuda_runtime.h>
#include <cuda_bf16.h>
#include <cstdint>

#define NMAX 50000
#define EMAX 800000
#define D 128

// ---------------- device scratch (no allocations allowed) ----------------
__device__ int   g_cnt[NMAX];
__device__ int   g_off[NMAX + 1];
__device__ int   g_cur[NMAX];
__device__ int   g_srcs[EMAX];
__device__ float g_attr[EMAX];
__device__ float g_h[3][NMAX * D];   // h1, h2, h3
__device__ float g_tmp[NMAX * D];
__device__ float g_mid[NMAX * D];
// prepacked weight chunks: 80 chunks (6 layer-GEMMs x 8 + final x 32).
// chunk = 128 n-rows x 40 bf16 (k 0..15 = hi, k 16..31 = lo, 32..39 pad).
__device__ __align__(16) __nv_bfloat16 g_wb[80][128 * 40];

// ---------------- preprocessing: CSR by target via counting sort ----------------
__global__ void k_zero(int n) {
    int i = blockIdx.x * blockDim.x + threadIdx.x;
    if (i < n) g_cnt[i] = 0;
}

__global__ void k_hist(const int* __restrict__ tgt, int E) {
    int i = blockIdx.x * blockDim.x + threadIdx.x;
    if (i < E) atomicAdd(&g_cnt[tgt[i]], 1);
}

__global__ void k_scan(int n) {
    __shared__ int wsum[32];
    __shared__ int carry;
    const int lane = threadIdx.x & 31;
    const int wid  = threadIdx.x >> 5;
    if (threadIdx.x == 0) { carry = 0; g_off[0] = 0; }
    __syncthreads();
    for (int base = 0; base < n; base += 1024) {
        int i = base + (int)threadIdx.x;
        int v = (i < n) ? g_cnt[i] : 0;
        int s = v;
        #pragma unroll
        for (int d = 1; d < 32; d <<= 1) {
            int t = __shfl_up_sync(0xFFFFFFFFu, s, d);
            if (lane >= d) s += t;
        }
        if (lane == 31) wsum[wid] = s;
        __syncthreads();
        if (wid == 0) {
            int ws = wsum[lane];
            #pragma unroll
            for (int d = 1; d < 32; d <<= 1) {
                int t = __shfl_up_sync(0xFFFFFFFFu, ws, d);
                if (lane >= d) ws += t;
            }
            wsum[lane] = ws;
        }
        __syncthreads();
        int incl = s + (wid ? wsum[wid - 1] : 0) + carry;
        if (i < n) {
            g_off[i + 1] = incl;
            g_cur[i]     = incl - v;
        }
        __syncthreads();
        if (threadIdx.x == 1023) carry = incl;
        __syncthreads();
    }
}

__global__ void k_scatter(const int* __restrict__ src, const int* __restrict__ tgt,
                          const float* __restrict__ ea, int E) {
    int i = blockIdx.x * blockDim.x + threadIdx.x;
    if (i < E) {
        int p = atomicAdd(&g_cur[tgt[i]], 1);
        g_srcs[p] = src[i];
        g_attr[p] = ea[i];
    }
}

// ---------------- aggregation: one warp per node ----------------
__global__ void k_agg(const float* __restrict__ h,
                      const float* __restrict__ lw, const float* __restrict__ lb,
                      const float* __restrict__ eps, int l,
                      float* __restrict__ out, int n) {
    int warp = (blockIdx.x * blockDim.x + threadIdx.x) >> 5;
    int lane = threadIdx.x & 31;
    if (warp >= n) return;
    int s0 = g_off[warp], s1 = g_off[warp + 1];
    float4 lw4 = *(const float4*)(lw + lane * 4);
    float4 lb4 = *(const float4*)(lb + lane * 4);
    float4 acc = make_float4(0.f, 0.f, 0.f, 0.f);
    #pragma unroll 4
    for (int e = s0; e < s1; ++e) {
        int   s = g_srcs[e];
        float a = g_attr[e];
        float4 hv = *(const float4*)(h + (size_t)s * D + lane * 4);
        acc.x += fmaxf(fmaf(a, lw4.x, lb4.x) + hv.x, 0.f);
        acc.y += fmaxf(fmaf(a, lw4.y, lb4.y) + hv.y, 0.f);
        acc.z += fmaxf(fmaf(a, lw4.z, lb4.z) + hv.z, 0.f);
        acc.w += fmaxf(fmaf(a, lw4.w, lb4.w) + hv.w, 0.f);
    }
    float inv = 1.f / (float)(s1 - s0);
    float g   = 1.f + eps[l];
    float4 hn = *(const float4*)(h + (size_t)warp * D + lane * 4);
    float4 o;
    o.x = acc.x * inv + g * hn.x;
    o.y = acc.y * inv + g * hn.y;
    o.z = acc.z * inv + g * hn.z;
    o.w = acc.w * inv + g * hn.w;
    *(float4*)(out + (size_t)warp * D + lane * 4) = o;
}

// ---------------- weight prep: transpose + bf16 split into g_wb ----------------
// 80 chunks: ch<48 -> GEMM g=ch/8 (layer g/2, W = g&1 ? w2 : w1), cw=ch&7;
//            ch>=48 -> final GEMM, cw=ch-48 (0..31).
// element: n in 0..127, kk in 0..15; kg = cw*16 + kk; val = W[kg*128 + n].
__global__ void k_wprep(const float* __restrict__ w1, const float* __restrict__ w2,
                        const float* __restrict__ fw) {
    int idx = blockIdx.x * blockDim.x + threadIdx.x;     // 80 * 128 * 16 = 163840
    if (idx >= 80 * 128 * 16) return;
    int ch  = idx >> 11;            // / (128*16)
    int rem = idx & 2047;
    int n   = rem >> 4;
    int kk  = rem & 15;
    const float* W;
    int kg;
    if (ch < 48) {
        int g  = ch >> 3;
        int cw = ch & 7;
        int layer = g >> 1;
        W  = (g & 1) ? (w2 + (size_t)layer * D * D) : (w1 + (size_t)layer * D * D);
        kg = cw * 16 + kk;
    } else {
        int cw = ch - 48;
        W  = fw;
        kg = cw * 16 + kk;
    }
    float v = W[(size_t)kg * 128 + n];
    __nv_bfloat16 hi = __float2bfloat16(v);
    __nv_bfloat16 lo = __float2bfloat16(v - __bfloat162float(hi));
    g_wb[ch][n * 40 + kk]      = hi;
    g_wb[ch][n * 40 + 16 + kk] = lo;
}

// ---------------- HMMA helper ----------------
__device__ __forceinline__ void mma_bf16(float* c, const uint32_t* a, uint32_t b0, uint32_t b1) {
    asm volatile(
        "mma.sync.aligned.m16n8k16.row.col.f32.bf16.bf16.f32 "
        "{%0,%1,%2,%3}, {%4,%5,%6,%7}, {%8,%9}, {%0,%1,%2,%3};"
        : "+f"(c[0]), "+f"(c[1]), "+f"(c[2]), "+f"(c[3])
        : "r"(a[0]), "r"(a[1]), "r"(a[2]), "r"(a[3]), "r"(b0), "r"(b1));
}

// ---------------- GEMM via mma.sync: C[M,128] = concat(A0..A{NSRC-1}) @ W + bias ----
// 128x128 tile per 256-thread CTA; K in 16-fp32 chunks, bf16 hi/lo 3-pass split.
// smem rows padded to 40 bf16 (20 banks) -> conflict-free fragment LDS.
template <int NSRC, bool RELU>
__global__ void __launch_bounds__(256) k_gemm_mma(
    const float* __restrict__ A0, const float* __restrict__ A1,
    const float* __restrict__ A2, const float* __restrict__ A3,
    int wbase, const float* __restrict__ bias, float* __restrict__ C, int M)
{
    __shared__ __align__(16) __nv_bfloat16 sA[128 * 40];
    __shared__ __align__(16) __nv_bfloat16 sB[128 * 40];

    const int tid  = threadIdx.x;
    const int w    = tid >> 5;
    const int lane = tid & 31;
    const int wr   = w & 3;          // warp row group: 32 rows
    const int wc   = w >> 2;         // warp col group: 64 cols
    const int gid  = lane >> 2;
    const int tg   = lane & 3;
    const int brow = blockIdx.x * 128;

    const float* srcs[4] = {A0, A1, A2, A3};

    float c[2][8][4];
    #pragma unroll
    for (int mt = 0; mt < 2; ++mt)
        #pragma unroll
        for (int nt = 0; nt < 8; ++nt)
            #pragma unroll
            for (int j = 0; j < 4; ++j) c[mt][nt][j] = 0.f;

    const int arow  = tid >> 1;        // staging: row this thread converts
    const int ahalf = tid & 1;         // which 8 of the 16 k-cols
    const int grow  = brow + arow;

    for (int ch = 0; ch < NSRC * 8; ++ch) {
        if (ch) __syncthreads();
        // ---- stage B (prepacked straight copy: 10240B = 640 uint4) ----
        {
            const uint4* wsrc = (const uint4*)g_wb[wbase + ch];
            uint4* bd = (uint4*)sB;
            #pragma unroll
            for (int i = 0; i < 3; ++i) {
                int t = tid + 256 * i;
                if (t < 640) bd[t] = wsrc[t];
            }
        }
        // ---- stage A: 8 fp32 -> bf16 hi/lo ----
        {
            float v[8];
            if (grow < M) {
                const float* ap = srcs[ch >> 3] + (size_t)grow * D + (ch & 7) * 16 + ahalf * 8;
                float4 f0 = *(const float4*)(ap);
                float4 f1 = *(const float4*)(ap + 4);
                v[0] = f0.x; v[1] = f0.y; v[2] = f0.z; v[3] = f0.w;
                v[4] = f1.x; v[5] = f1.y; v[6] = f1.z; v[7] = f1.w;
            } else {
                #pragma unroll
                for (int i = 0; i < 8; ++i) v[i] = 0.f;
            }
            uint32_t hw[4], lw_[4];
            #pragma unroll
            for (int q = 0; q < 4; ++q) {
                __nv_bfloat16 h0 = __float2bfloat16(v[q * 2]);
                __nv_bfloat16 h1 = __float2bfloat16(v[q * 2 + 1]);
                __nv_bfloat16 l0 = __float2bfloat16(v[q * 2]     - __bfloat162float(h0));
                __nv_bfloat16 l1 = __float2bfloat16(v[q * 2 + 1] - __bfloat162float(h1));
                __nv_bfloat162 hp = {h0, h1}, lp = {l0, l1};
                hw[q]  = *(uint32_t*)&hp;
                lw_[q] = *(uint32_t*)&lp;
            }
            *(uint4*)&sA[arow * 40 + ahalf * 8]      = *(uint4*)hw;
            *(uint4*)&sA[arow * 40 + 16 + ahalf * 8] = *(uint4*)lw_;
        }
        __syncthreads();

        // ---- 3 passes: (Ahi,Bhi), (Alo,Bhi), (Ahi,Blo) ----
        #pragma unroll
        for (int p = 0; p < 3; ++p) {
            const int ak = (p == 1) ? 16 : 0;
            const int bk = (p == 2) ? 16 : 0;
            uint32_t a[2][4];
            #pragma unroll
            for (int mt = 0; mt < 2; ++mt) {
                int base = (wr * 32 + mt * 16 + gid) * 40 + ak + tg * 2;
                a[mt][0] = *(const uint32_t*)&sA[base];
                a[mt][1] = *(const uint32_t*)&sA[base + 8 * 40];
                a[mt][2] = *(const uint32_t*)&sA[base + 8];
                a[mt][3] = *(const uint32_t*)&sA[base + 8 * 40 + 8];
            }
            #pragma unroll
            for (int nt = 0; nt < 8; ++nt) {
                int nb = (wc * 64 + nt * 8 + gid) * 40 + bk + tg * 2;
                uint32_t b0 = *(const uint32_t*)&sB[nb];
                uint32_t b1 = *(const uint32_t*)&sB[nb + 8];
                mma_bf16(c[0][nt], a[0], b0, b1);
                mma_bf16(c[1][nt], a[1], b0, b1);
            }
        }
    }

    // ---- epilogue ----
    #pragma unroll
    for (int mt = 0; mt < 2; ++mt) {
        #pragma unroll
        for (int nt = 0; nt < 8; ++nt) {
            int col  = wc * 64 + nt * 8 + tg * 2;
            float bx = bias[col], by = bias[col + 1];
            int r0 = brow + wr * 32 + mt * 16 + gid;
            float v0 = c[mt][nt][0] + bx, v1 = c[mt][nt][1] + by;
            float v2 = c[mt][nt][2] + bx, v3 = c[mt][nt][3] + by;
            if (RELU) {
                v0 = fmaxf(v0, 0.f); v1 = fmaxf(v1, 0.f);
                v2 = fmaxf(v2, 0.f); v3 = fmaxf(v3, 0.f);
            }
            if (r0 < M)     *(float2*)(C + (size_t)r0 * D + col)       = make_float2(v0, v1);
            if (r0 + 8 < M) *(float2*)(C + (size_t)(r0 + 8) * D + col) = make_float2(v2, v3);
        }
    }
}

// ---------------- launcher ----------------
extern "C" void kernel_launch(void* const* d_in, const int* in_sizes, int n_in,
                              void* d_out, int out_size) {
    const float* x   = (const float*)d_in[0];
    const int*   ei  = (const int*)  d_in[1];   // [2, E]: row0 = src, row1 = tgt
    const float* ea  = (const float*)d_in[2];   // [E, 1]
    const float* lw  = (const float*)d_in[3];   // [3, 1, 128]
    const float* lb  = (const float*)d_in[4];   // [3, 128]
    const float* eps = (const float*)d_in[5];   // [3]
    const float* w1  = (const float*)d_in[6];   // [3, 128, 128]
    const float* b1  = (const float*)d_in[7];
    const float* w2  = (const float*)d_in[8];
    const float* b2  = (const float*)d_in[9];
    const float* fw  = (const float*)d_in[10];  // [512, 128]
    const float* fb  = (const float*)d_in[11];  // [128]
    float* out = (float*)d_out;

    const int N = in_sizes[0] / D;
    const int E = in_sizes[2];

    float *hbuf, *tmp, *mid;
    cudaGetSymbolAddress((void**)&hbuf, g_h);
    cudaGetSymbolAddress((void**)&tmp,  g_tmp);
    cudaGetSymbolAddress((void**)&mid,  g_mid);

    // weight prep + CSR build
    k_wprep<<<(80 * 128 * 16 + 255) / 256, 256>>>(w1, w2, fw);
    k_zero<<<(N + 255) / 256, 256>>>(N);
    k_hist<<<(E + 255) / 256, 256>>>(ei + E, E);
    k_scan<<<1, 1024>>>(N);
    k_scatter<<<(E + 255) / 256, 256>>>(ei, ei + E, ea, E);

    const int gb = (N + 127) / 128;
    const float* h = x;
    for (int l = 0; l < 3; ++l) {
        float* hl = hbuf + (size_t)l * NMAX * D;
        k_agg<<<(N + 7) / 8, 256>>>(h, lw + l * D, lb + l * D, eps, l, tmp, N);
        k_gemm_mma<1, true ><<<gb, 256>>>(tmp, nullptr, nullptr, nullptr,
                                          (l * 2 + 0) * 8, b1 + l * D, mid, N);
        k_gemm_mma<1, false><<<gb, 256>>>(mid, nullptr, nullptr, nullptr,
                                          (l * 2 + 1) * 8, b2 + l * D, hl, N);
        h = hl;
    }

    // final: [x | h1 | h2 | h3] @ fw + fb
    k_gemm_mma<4, false><<<gb, 256>>>(x, hbuf, hbuf + (size_t)NMAX * D,
                                      hbuf + (size_t)2 * NMAX * D, 48, fb, out, N);
}

// round 5
// speedup vs baseline: 1.6467x; 1.0877x over previous
#include <cuda_runtime.h>
#include <cuda_bf16.h>
#include <cstdint>

#define NMAX 50000
#define EMAX 800000
#define D 128

// ---------------- device scratch (no allocations allowed) ----------------
__device__ int   g_cnt[NMAX];
__device__ int   g_off[NMAX + 1];
__device__ int   g_cur[NMAX];
__device__ int2  g_edge[EMAX];       // {src, attr-bits}
__device__ int   g_bsum[64];
__device__ int   g_bpre[64];
__device__ float g_h[3][NMAX * D];   // h1, h2, h3
__device__ float g_tmp[NMAX * D];
__device__ float g_mid[NMAX * D];
// prepacked weight chunks: 80 chunks (6 layer-GEMMs x 8 + final x 32).
// chunk = 128 n-rows x 40 bf16 (k 0..15 = hi, k 16..31 = lo, 32..39 pad).
__device__ __align__(16) __nv_bfloat16 g_wb[80][128 * 40];

// ---------------- preprocessing: CSR by target via counting sort ----------------
__global__ void k_zero(int n) {
    int i = blockIdx.x * blockDim.x + threadIdx.x;
    if (i < n) g_cnt[i] = 0;
}

__global__ void k_hist(const int* __restrict__ tgt, int E) {
    int i = blockIdx.x * blockDim.x + threadIdx.x;
    if (i < E) atomicAdd(&g_cnt[tgt[i]], 1);
}

// block-local inclusive scan helper (1024 threads)
__device__ __forceinline__ int block_scan_incl(int v) {
    __shared__ int wsum[32];
    const int lane = threadIdx.x & 31;
    const int wid  = threadIdx.x >> 5;
    int s = v;
    #pragma unroll
    for (int d = 1; d < 32; d <<= 1) {
        int t = __shfl_up_sync(0xFFFFFFFFu, s, d);
        if (lane >= d) s += t;
    }
    if (lane == 31) wsum[wid] = s;
    __syncthreads();
    if (wid == 0) {
        int ws = (lane < 32) ? wsum[lane] : 0;
        #pragma unroll
        for (int d = 1; d < 32; d <<= 1) {
            int t = __shfl_up_sync(0xFFFFFFFFu, ws, d);
            if (lane >= d) ws += t;
        }
        wsum[lane] = ws;
    }
    __syncthreads();
    return s + (wid ? wsum[wid - 1] : 0);
}

// phase 1: per-block inclusive scan of g_cnt -> g_off[i+1] (block-local), block totals
__global__ void k_scan1(int n) {
    int i = blockIdx.x * 1024 + threadIdx.x;
    int v = (i < n) ? g_cnt[i] : 0;
    int incl = block_scan_incl(v);
    if (i < n) g_off[i + 1] = incl;
    if (threadIdx.x == 1023) g_bsum[blockIdx.x] = incl;
}

// phase 2: exclusive scan of block totals (nb <= 64, one warp handles 2 elems/lane)
__global__ void k_scan2(int nb) {
    int lane = threadIdx.x;           // 32 threads
    int v0 = (lane      < nb) ? g_bsum[lane]      : 0;
    int v1 = (lane + 32 < nb) ? g_bsum[lane + 32] : 0;
    int s = v0;
    #pragma unroll
    for (int d = 1; d < 32; d <<= 1) {
        int t = __shfl_up_sync(0xFFFFFFFFu, s, d);
        if (lane >= d) s += t;
    }
    int tot0 = __shfl_sync(0xFFFFFFFFu, s, 31);
    int s1 = v1;
    #pragma unroll
    for (int d = 1; d < 32; d <<= 1) {
        int t = __shfl_up_sync(0xFFFFFFFFu, s1, d);
        if (lane >= d) s1 += t;
    }
    if (lane < nb)      g_bpre[lane]      = s - v0;               // exclusive
    if (lane + 32 < nb) g_bpre[lane + 32] = tot0 + s1 - v1;
}

// phase 3: add block prefix, derive cursors
__global__ void k_scan3(int n) {
    int i = blockIdx.x * 1024 + threadIdx.x;
    if (i < n) {
        int off = g_off[i + 1] + g_bpre[blockIdx.x];
        g_off[i + 1] = off;
        g_cur[i]     = off - g_cnt[i];
    }
    if (i == 0) g_off[0] = 0;
}

__global__ void k_scatter(const int* __restrict__ src, const int* __restrict__ tgt,
                          const float* __restrict__ ea, int E) {
    int i = blockIdx.x * blockDim.x + threadIdx.x;
    if (i < E) {
        int p = atomicAdd(&g_cur[tgt[i]], 1);
        g_edge[p] = make_int2(src[i], __float_as_int(ea[i]));
    }
}

// ---------------- aggregation: one warp per node ----------------
__global__ void k_agg(const float* __restrict__ h,
                      const float* __restrict__ lw, const float* __restrict__ lb,
                      const float* __restrict__ eps, int l,
                      float* __restrict__ out, int n) {
    int warp = (blockIdx.x * blockDim.x + threadIdx.x) >> 5;
    int lane = threadIdx.x & 31;
    if (warp >= n) return;
    int s0 = g_off[warp], s1 = g_off[warp + 1];
    float4 lw4 = *(const float4*)(lw + lane * 4);
    float4 lb4 = *(const float4*)(lb + lane * 4);
    float4 acc = make_float4(0.f, 0.f, 0.f, 0.f);
    #pragma unroll 4
    for (int e = s0; e < s1; ++e) {
        int2  p = g_edge[e];
        float a = __int_as_float(p.y);
        float4 hv = *(const float4*)(h + (size_t)p.x * D + lane * 4);
        acc.x += fmaxf(fmaf(a, lw4.x, lb4.x) + hv.x, 0.f);
        acc.y += fmaxf(fmaf(a, lw4.y, lb4.y) + hv.y, 0.f);
        acc.z += fmaxf(fmaf(a, lw4.z, lb4.z) + hv.z, 0.f);
        acc.w += fmaxf(fmaf(a, lw4.w, lb4.w) + hv.w, 0.f);
    }
    float inv = 1.f / (float)(s1 - s0);
    float g   = 1.f + eps[l];
    float4 hn = *(const float4*)(h + (size_t)warp * D + lane * 4);
    float4 o;
    o.x = acc.x * inv + g * hn.x;
    o.y = acc.y * inv + g * hn.y;
    o.z = acc.z * inv + g * hn.z;
    o.w = acc.w * inv + g * hn.w;
    *(float4*)(out + (size_t)warp * D + lane * 4) = o;
}

// ---------------- weight prep: transpose + bf16 split into g_wb ----------------
__global__ void k_wprep(const float* __restrict__ w1, const float* __restrict__ w2,
                        const float* __restrict__ fw) {
    int idx = blockIdx.x * blockDim.x + threadIdx.x;     // 80 * 128 * 16 = 163840
    if (idx >= 80 * 128 * 16) return;
    int ch  = idx >> 11;
    int rem = idx & 2047;
    int n   = rem >> 4;
    int kk  = rem & 15;
    const float* W;
    int kg;
    if (ch < 48) {
        int g  = ch >> 3;
        int cw = ch & 7;
        int layer = g >> 1;
        W  = (g & 1) ? (w2 + (size_t)layer * D * D) : (w1 + (size_t)layer * D * D);
        kg = cw * 16 + kk;
    } else {
        int cw = ch - 48;
        W  = fw;
        kg = cw * 16 + kk;
    }
    float v = W[(size_t)kg * 128 + n];
    __nv_bfloat16 hi = __float2bfloat16(v);
    __nv_bfloat16 lo = __float2bfloat16(v - __bfloat162float(hi));
    g_wb[ch][n * 40 + kk]      = hi;
    g_wb[ch][n * 40 + 16 + kk] = lo;
}

// ---------------- HMMA helper ----------------
__device__ __forceinline__ void mma_bf16(float* c, const uint32_t* a, uint32_t b0, uint32_t b1) {
    asm volatile(
        "mma.sync.aligned.m16n8k16.row.col.f32.bf16.bf16.f32 "
        "{%0,%1,%2,%3}, {%4,%5,%6,%7}, {%8,%9}, {%0,%1,%2,%3};"
        : "+f"(c[0]), "+f"(c[1]), "+f"(c[2]), "+f"(c[3])
        : "r"(a[0]), "r"(a[1]), "r"(a[2]), "r"(a[3]), "r"(b0), "r"(b1));
}

// ---------------- GEMM via mma.sync: C[M,128] = concat(A0..A{NSRC-1}) @ W + bias ----
template <int NSRC, bool RELU>
__global__ void __launch_bounds__(256) k_gemm_mma(
    const float* __restrict__ A0, const float* __restrict__ A1,
    const float* __restrict__ A2, const float* __restrict__ A3,
    int wbase, const float* __restrict__ bias, float* __restrict__ C, int M)
{
    __shared__ __align__(16) __nv_bfloat16 sA[128 * 40];
    __shared__ __align__(16) __nv_bfloat16 sB[128 * 40];

    const int tid  = threadIdx.x;
    const int w    = tid >> 5;
    const int lane = tid & 31;
    const int wr   = w & 3;
    const int wc   = w >> 2;
    const int gid  = lane >> 2;
    const int tg   = lane & 3;
    const int brow = blockIdx.x * 128;

    const float* srcs[4] = {A0, A1, A2, A3};

    float c[2][8][4];
    #pragma unroll
    for (int mt = 0; mt < 2; ++mt)
        #pragma unroll
        for (int nt = 0; nt < 8; ++nt)
            #pragma unroll
            for (int j = 0; j < 4; ++j) c[mt][nt][j] = 0.f;

    const int arow  = tid >> 1;
    const int ahalf = tid & 1;
    const int grow  = brow + arow;

    for (int ch = 0; ch < NSRC * 8; ++ch) {
        if (ch) __syncthreads();
        // ---- stage B (prepacked straight copy: 640 uint4) ----
        {
            const uint4* wsrc = (const uint4*)g_wb[wbase + ch];
            uint4* bd = (uint4*)sB;
            #pragma unroll
            for (int i = 0; i < 3; ++i) {
                int t = tid + 256 * i;
                if (t < 640) bd[t] = wsrc[t];
            }
        }
        // ---- stage A: 8 fp32 -> bf16 hi/lo ----
        {
            float v[8];
            if (grow < M) {
                const float* ap = srcs[ch >> 3] + (size_t)grow * D + (ch & 7) * 16 + ahalf * 8;
                float4 f0 = *(const float4*)(ap);
                float4 f1 = *(const float4*)(ap + 4);
                v[0] = f0.x; v[1] = f0.y; v[2] = f0.z; v[3] = f0.w;
                v[4] = f1.x; v[5] = f1.y; v[6] = f1.z; v[7] = f1.w;
            } else {
                #pragma unroll
                for (int i = 0; i < 8; ++i) v[i] = 0.f;
            }
            uint32_t hw[4], lw_[4];
            #pragma unroll
            for (int q = 0; q < 4; ++q) {
                __nv_bfloat16 h0 = __float2bfloat16(v[q * 2]);
                __nv_bfloat16 h1 = __float2bfloat16(v[q * 2 + 1]);
                __nv_bfloat16 l0 = __float2bfloat16(v[q * 2]     - __bfloat162float(h0));
                __nv_bfloat16 l1 = __float2bfloat16(v[q * 2 + 1] - __bfloat162float(h1));
                __nv_bfloat162 hp = {h0, h1}, lp = {l0, l1};
                hw[q]  = *(uint32_t*)&hp;
                lw_[q] = *(uint32_t*)&lp;
            }
            *(uint4*)&sA[arow * 40 + ahalf * 8]      = *(uint4*)hw;
            *(uint4*)&sA[arow * 40 + 16 + ahalf * 8] = *(uint4*)lw_;
        }
        __syncthreads();

        // ---- 3 passes: (Ahi,Bhi), (Alo,Bhi), (Ahi,Blo) ----
        #pragma unroll
        for (int p = 0; p < 3; ++p) {
            const int ak = (p == 1) ? 16 : 0;
            const int bk = (p == 2) ? 16 : 0;
            uint32_t a[2][4];
            #pragma unroll
            for (int mt = 0; mt < 2; ++mt) {
                int base = (wr * 32 + mt * 16 + gid) * 40 + ak + tg * 2;
                a[mt][0] = *(const uint32_t*)&sA[base];
                a[mt][1] = *(const uint32_t*)&sA[base + 8 * 40];
                a[mt][2] = *(const uint32_t*)&sA[base + 8];
                a[mt][3] = *(const uint32_t*)&sA[base + 8 * 40 + 8];
            }
            #pragma unroll
            for (int nt = 0; nt < 8; ++nt) {
                int nb = (wc * 64 + nt * 8 + gid) * 40 + bk + tg * 2;
                uint32_t b0 = *(const uint32_t*)&sB[nb];
                uint32_t b1 = *(const uint32_t*)&sB[nb + 8];
                mma_bf16(c[0][nt], a[0], b0, b1);
                mma_bf16(c[1][nt], a[1], b0, b1);
            }
        }
    }

    // ---- epilogue ----
    #pragma unroll
    for (int mt = 0; mt < 2; ++mt) {
        #pragma unroll
        for (int nt = 0; nt < 8; ++nt) {
            int col  = wc * 64 + nt * 8 + tg * 2;
            float bx = bias[col], by = bias[col + 1];
            int r0 = brow + wr * 32 + mt * 16 + gid;
            float v0 = c[mt][nt][0] + bx, v1 = c[mt][nt][1] + by;
            float v2 = c[mt][nt][2] + bx, v3 = c[mt][nt][3] + by;
            if (RELU) {
                v0 = fmaxf(v0, 0.f); v1 = fmaxf(v1, 0.f);
                v2 = fmaxf(v2, 0.f); v3 = fmaxf(v3, 0.f);
            }
            if (r0 < M)     *(float2*)(C + (size_t)r0 * D + col)       = make_float2(v0, v1);
            if (r0 + 8 < M) *(float2*)(C + (size_t)(r0 + 8) * D + col) = make_float2(v2, v3);
        }
    }
}

// ---------------- launcher ----------------
extern "C" void kernel_launch(void* const* d_in, const int* in_sizes, int n_in,
                              void* d_out, int out_size) {
    const float* x   = (const float*)d_in[0];
    const int*   ei  = (const int*)  d_in[1];
    const float* ea  = (const float*)d_in[2];
    const float* lw  = (const float*)d_in[3];
    const float* lb  = (const float*)d_in[4];
    const float* eps = (const float*)d_in[5];
    const float* w1  = (const float*)d_in[6];
    const float* b1  = (const float*)d_in[7];
    const float* w2  = (const float*)d_in[8];
    const float* b2  = (const float*)d_in[9];
    const float* fw  = (const float*)d_in[10];
    const float* fb  = (const float*)d_in[11];
    float* out = (float*)d_out;

    const int N = in_sizes[0] / D;
    const int E = in_sizes[2];

    float *hbuf, *tmp, *mid;
    cudaGetSymbolAddress((void**)&hbuf, g_h);
    cudaGetSymbolAddress((void**)&tmp,  g_tmp);
    cudaGetSymbolAddress((void**)&mid,  g_mid);

    // weight prep + CSR build
    k_wprep<<<(80 * 128 * 16 + 255) / 256, 256>>>(w1, w2, fw);
    k_zero<<<(N + 255) / 256, 256>>>(N);
    k_hist<<<(E + 255) / 256, 256>>>(ei + E, E);
    const int nb = (N + 1023) / 1024;
    k_scan1<<<nb, 1024>>>(N);
    k_scan2<<<1, 32>>>(nb);
    k_scan3<<<nb, 1024>>>(N);
    k_scatter<<<(E + 255) / 256, 256>>>(ei, ei + E, ea, E);

    const int gb = (N + 127) / 128;
    const float* h = x;
    for (int l = 0; l < 3; ++l) {
        float* hl = hbuf + (size_t)l * NMAX * D;
        k_agg<<<(N + 7) / 8, 256>>>(h, lw + l * D, lb + l * D, eps, l, tmp, N);
        k_gemm_mma<1, true ><<<gb, 256>>>(tmp, nullptr, nullptr, nullptr,
                                          (l * 2 + 0) * 8, b1 + l * D, mid, N);
        k_gemm_mma<1, false><<<gb, 256>>>(mid, nullptr, nullptr, nullptr,
                                          (l * 2 + 1) * 8, b2 + l * D, hl, N);
        h = hl;
    }

    // final: [x | h1 | h2 | h3] @ fw + fb
    k_gemm_mma<4, false><<<gb, 256>>>(x, hbuf, hbuf + (size_t)NMAX * D,
                                      hbuf + (size_t)2 * NMAX * D, 48, fb, out, N);
}

// round 6
// speedup vs baseline: 1.7548x; 1.0656x over previous
#include <cuda_runtime.h>
#include <cuda_bf16.h>
#include <cstdint>

#define NMAX 50000
#define EMAX 800000
#define D 128

// ---------------- device scratch (no allocations allowed) ----------------
__device__ int   g_cnt[NMAX];
__device__ int   g_off[NMAX + 1];
__device__ int   g_cur[NMAX];
__device__ int2  g_edge[EMAX];       // {src, attr-bits}
__device__ int   g_bsum[64];
__device__ int   g_bpre[64];
__device__ float g_h[3][NMAX * D];   // h1, h2, h3
__device__ float g_tmp[NMAX * D];
// prepacked weight chunks: 80 chunks (6 layer-GEMMs x 8 + final x 32).
// chunk = 128 n-rows x 40 bf16 (k 0..15 = hi, k 16..31 = lo, 32..39 pad).
__device__ __align__(16) __nv_bfloat16 g_wb[80][128 * 40];

// ---------------- preprocessing: CSR by target via counting sort ----------------
__global__ void k_zero(int n) {
    int i = blockIdx.x * blockDim.x + threadIdx.x;
    if (i < n) g_cnt[i] = 0;
}

__global__ void k_hist(const int* __restrict__ tgt, int E) {
    int i = blockIdx.x * blockDim.x + threadIdx.x;
    if (i < E) atomicAdd(&g_cnt[tgt[i]], 1);
}

__device__ __forceinline__ int block_scan_incl(int v) {
    __shared__ int wsum[32];
    const int lane = threadIdx.x & 31;
    const int wid  = threadIdx.x >> 5;
    int s = v;
    #pragma unroll
    for (int d = 1; d < 32; d <<= 1) {
        int t = __shfl_up_sync(0xFFFFFFFFu, s, d);
        if (lane >= d) s += t;
    }
    if (lane == 31) wsum[wid] = s;
    __syncthreads();
    if (wid == 0) {
        int ws = wsum[lane];
        #pragma unroll
        for (int d = 1; d < 32; d <<= 1) {
            int t = __shfl_up_sync(0xFFFFFFFFu, ws, d);
            if (lane >= d) ws += t;
        }
        wsum[lane] = ws;
    }
    __syncthreads();
    return s + (wid ? wsum[wid - 1] : 0);
}

__global__ void k_scan1(int n) {
    int i = blockIdx.x * 1024 + threadIdx.x;
    int v = (i < n) ? g_cnt[i] : 0;
    int incl = block_scan_incl(v);
    if (i < n) g_off[i + 1] = incl;
    if (threadIdx.x == 1023) g_bsum[blockIdx.x] = incl;
}

__global__ void k_scan2(int nb) {
    int lane = threadIdx.x;           // 32 threads
    int v0 = (lane      < nb) ? g_bsum[lane]      : 0;
    int v1 = (lane + 32 < nb) ? g_bsum[lane + 32] : 0;
    int s = v0;
    #pragma unroll
    for (int d = 1; d < 32; d <<= 1) {
        int t = __shfl_up_sync(0xFFFFFFFFu, s, d);
        if (lane >= d) s += t;
    }
    int tot0 = __shfl_sync(0xFFFFFFFFu, s, 31);
    int s1 = v1;
    #pragma unroll
    for (int d = 1; d < 32; d <<= 1) {
        int t = __shfl_up_sync(0xFFFFFFFFu, s1, d);
        if (lane >= d) s1 += t;
    }
    if (lane < nb)      g_bpre[lane]      = s - v0;
    if (lane + 32 < nb) g_bpre[lane + 32] = tot0 + s1 - v1;
}

__global__ void k_scan3(int n) {
    int i = blockIdx.x * 1024 + threadIdx.x;
    if (i < n) {
        int off = g_off[i + 1] + g_bpre[blockIdx.x];
        g_off[i + 1] = off;
        g_cur[i]     = off - g_cnt[i];
    }
    if (i == 0) g_off[0] = 0;
}

__global__ void k_scatter(const int* __restrict__ src, const int* __restrict__ tgt,
                          const float* __restrict__ ea, int E) {
    int i = blockIdx.x * blockDim.x + threadIdx.x;
    if (i < E) {
        int p = atomicAdd(&g_cur[tgt[i]], 1);
        g_edge[p] = make_int2(src[i], __float_as_int(ea[i]));
    }
}

// ---------------- aggregation: one warp per node ----------------
__global__ void k_agg(const float* __restrict__ h,
                      const float* __restrict__ lw, const float* __restrict__ lb,
                      const float* __restrict__ eps, int l,
                      float* __restrict__ out, int n) {
    int warp = (blockIdx.x * blockDim.x + threadIdx.x) >> 5;
    int lane = threadIdx.x & 31;
    if (warp >= n) return;
    int s0 = g_off[warp], s1 = g_off[warp + 1];
    float4 lw4 = *(const float4*)(lw + lane * 4);
    float4 lb4 = *(const float4*)(lb + lane * 4);
    float4 acc = make_float4(0.f, 0.f, 0.f, 0.f);
    #pragma unroll 4
    for (int e = s0; e < s1; ++e) {
        int2  p = g_edge[e];
        float a = __int_as_float(p.y);
        float4 hv = *(const float4*)(h + (size_t)p.x * D + lane * 4);
        acc.x += fmaxf(fmaf(a, lw4.x, lb4.x) + hv.x, 0.f);
        acc.y += fmaxf(fmaf(a, lw4.y, lb4.y) + hv.y, 0.f);
        acc.z += fmaxf(fmaf(a, lw4.z, lb4.z) + hv.z, 0.f);
        acc.w += fmaxf(fmaf(a, lw4.w, lb4.w) + hv.w, 0.f);
    }
    float inv = 1.f / (float)(s1 - s0);
    float g   = 1.f + eps[l];
    float4 hn = *(const float4*)(h + (size_t)warp * D + lane * 4);
    float4 o;
    o.x = acc.x * inv + g * hn.x;
    o.y = acc.y * inv + g * hn.y;
    o.z = acc.z * inv + g * hn.z;
    o.w = acc.w * inv + g * hn.w;
    *(float4*)(out + (size_t)warp * D + lane * 4) = o;
}

// ---------------- weight prep: transpose + bf16 split into g_wb ----------------
__global__ void k_wprep(const float* __restrict__ w1, const float* __restrict__ w2,
                        const float* __restrict__ fw) {
    int idx = blockIdx.x * blockDim.x + threadIdx.x;     // 80 * 128 * 16 = 163840
    if (idx >= 80 * 128 * 16) return;
    int ch  = idx >> 11;
    int rem = idx & 2047;
    int n   = rem >> 4;
    int kk  = rem & 15;
    const float* W;
    int kg;
    if (ch < 48) {
        int g  = ch >> 3;
        int cw = ch & 7;
        int layer = g >> 1;
        W  = (g & 1) ? (w2 + (size_t)layer * D * D) : (w1 + (size_t)layer * D * D);
        kg = cw * 16 + kk;
    } else {
        int cw = ch - 48;
        W  = fw;
        kg = cw * 16 + kk;
    }
    float v = W[(size_t)kg * 128 + n];
    __nv_bfloat16 hi = __float2bfloat16(v);
    __nv_bfloat16 lo = __float2bfloat16(v - __bfloat162float(hi));
    g_wb[ch][n * 40 + kk]      = hi;
    g_wb[ch][n * 40 + 16 + kk] = lo;
}

// ---------------- HMMA helper ----------------
__device__ __forceinline__ void mma_bf16(float* c, const uint32_t* a, uint32_t b0, uint32_t b1) {
    asm volatile(
        "mma.sync.aligned.m16n8k16.row.col.f32.bf16.bf16.f32 "
        "{%0,%1,%2,%3}, {%4,%5,%6,%7}, {%8,%9}, {%0,%1,%2,%3};"
        : "+f"(c[0]), "+f"(c[1]), "+f"(c[2]), "+f"(c[3])
        : "r"(a[0]), "r"(a[1]), "r"(a[2]), "r"(a[3]), "r"(b0), "r"(b1));
}

__device__ __forceinline__ void split_bf16(float v, __nv_bfloat16& hi, __nv_bfloat16& lo) {
    hi = __float2bfloat16(v);
    lo = __float2bfloat16(v - __bfloat162float(hi));
}

// ---------------- fused layer MLP: h = relu(A@w1+b1)@w2+b2 ----------------
// 64x128 tile per 256-thread CTA. 8 warps: wr = w&1 (32 rows), wc = w>>1 (32 cols).
// sU aliases: phase-1 A staging (64x40) then sMid (64x264: cols 0..127 hi, 128..255 lo).
__global__ void __launch_bounds__(256) k_layer_mlp(
    const float* __restrict__ A, int wb1, int wb2,
    const float* __restrict__ bias1, const float* __restrict__ bias2,
    float* __restrict__ Cout, int M)
{
    __shared__ __align__(16) __nv_bfloat16 sU[64 * 264];
    __shared__ __align__(16) __nv_bfloat16 sB[128 * 40];

    const int tid  = threadIdx.x;
    const int w    = tid >> 5;
    const int lane = tid & 31;
    const int wr   = w & 1;
    const int wc   = w >> 1;
    const int gid  = lane >> 2;
    const int tg   = lane & 3;
    const int brow = blockIdx.x * 64;

    float c[2][4][4];
    #pragma unroll
    for (int mt = 0; mt < 2; ++mt)
        #pragma unroll
        for (int nt = 0; nt < 4; ++nt)
            #pragma unroll
            for (int j = 0; j < 4; ++j) c[mt][nt][j] = 0.f;

    const int arow = tid >> 2;       // 0..63
    const int aq   = tid & 3;        // 4 fp32 each
    const int grow = brow + arow;

    // ================= phase 1: mid = A @ w1 =================
    for (int ch = 0; ch < 8; ++ch) {
        if (ch) __syncthreads();
        {   // stage B chunk
            const uint4* wsrc = (const uint4*)g_wb[wb1 + ch];
            uint4* bd = (uint4*)sB;
            #pragma unroll
            for (int i = 0; i < 3; ++i) {
                int t = tid + 256 * i;
                if (t < 640) bd[t] = wsrc[t];
            }
        }
        {   // stage A: 4 fp32 -> bf16 hi/lo
            float v[4];
            if (grow < M) {
                float4 f = *(const float4*)(A + (size_t)grow * D + ch * 16 + aq * 4);
                v[0] = f.x; v[1] = f.y; v[2] = f.z; v[3] = f.w;
            } else {
                v[0] = v[1] = v[2] = v[3] = 0.f;
            }
            uint32_t hw[2], lw_[2];
            #pragma unroll
            for (int q = 0; q < 2; ++q) {
                __nv_bfloat16 h0, l0, h1, l1;
                split_bf16(v[q * 2],     h0, l0);
                split_bf16(v[q * 2 + 1], h1, l1);
                __nv_bfloat162 hp = {h0, h1}, lp = {l0, l1};
                hw[q]  = *(uint32_t*)&hp;
                lw_[q] = *(uint32_t*)&lp;
            }
            *(uint2*)&sU[arow * 40 + aq * 4]      = *(uint2*)hw;
            *(uint2*)&sU[arow * 40 + 16 + aq * 4] = *(uint2*)lw_;
        }
        __syncthreads();

        #pragma unroll
        for (int p = 0; p < 3; ++p) {
            const int ak = (p == 1) ? 16 : 0;
            const int bk = (p == 2) ? 16 : 0;
            uint32_t a[2][4];
            #pragma unroll
            for (int mt = 0; mt < 2; ++mt) {
                int base = (wr * 32 + mt * 16 + gid) * 40 + ak + tg * 2;
                a[mt][0] = *(const uint32_t*)&sU[base];
                a[mt][1] = *(const uint32_t*)&sU[base + 8 * 40];
                a[mt][2] = *(const uint32_t*)&sU[base + 8];
                a[mt][3] = *(const uint32_t*)&sU[base + 8 * 40 + 8];
            }
            #pragma unroll
            for (int nt = 0; nt < 4; ++nt) {
                int nb = (wc * 32 + nt * 8 + gid) * 40 + bk + tg * 2;
                uint32_t b0 = *(const uint32_t*)&sB[nb];
                uint32_t b1 = *(const uint32_t*)&sB[nb + 8];
                mma_bf16(c[0][nt], a[0], b0, b1);
                mma_bf16(c[1][nt], a[1], b0, b1);
            }
        }
    }
    __syncthreads();   // sA region dead; safe to overwrite as sMid

    // ============ epilogue 1: bias + relu + bf16 split -> sMid ============
    #pragma unroll
    for (int mt = 0; mt < 2; ++mt) {
        #pragma unroll
        for (int nt = 0; nt < 4; ++nt) {
            int col = wc * 32 + nt * 8 + tg * 2;
            float bx = bias1[col], by = bias1[col + 1];
            #pragma unroll
            for (int half = 0; half < 2; ++half) {
                int r = wr * 32 + mt * 16 + gid + half * 8;
                float v0 = fmaxf(c[mt][nt][half * 2]     + bx, 0.f);
                float v1 = fmaxf(c[mt][nt][half * 2 + 1] + by, 0.f);
                __nv_bfloat16 h0, l0, h1, l1;
                split_bf16(v0, h0, l0);
                split_bf16(v1, h1, l1);
                __nv_bfloat162 hp = {h0, h1}, lp = {l0, l1};
                *(uint32_t*)&sU[r * 264 + col]       = *(uint32_t*)&hp;
                *(uint32_t*)&sU[r * 264 + 128 + col] = *(uint32_t*)&lp;
            }
        }
    }
    __syncthreads();

    // ================= phase 2: h = mid @ w2 =================
    #pragma unroll
    for (int mt = 0; mt < 2; ++mt)
        #pragma unroll
        for (int nt = 0; nt < 4; ++nt)
            #pragma unroll
            for (int j = 0; j < 4; ++j) c[mt][nt][j] = 0.f;

    for (int ch = 0; ch < 8; ++ch) {
        if (ch) __syncthreads();
        {
            const uint4* wsrc = (const uint4*)g_wb[wb2 + ch];
            uint4* bd = (uint4*)sB;
            #pragma unroll
            for (int i = 0; i < 3; ++i) {
                int t = tid + 256 * i;
                if (t < 640) bd[t] = wsrc[t];
            }
        }
        __syncthreads();

        #pragma unroll
        for (int p = 0; p < 3; ++p) {
            const int ak = ch * 16 + ((p == 1) ? 128 : 0);
            const int bk = (p == 2) ? 16 : 0;
            uint32_t a[2][4];
            #pragma unroll
            for (int mt = 0; mt < 2; ++mt) {
                int base = (wr * 32 + mt * 16 + gid) * 264 + ak + tg * 2;
                a[mt][0] = *(const uint32_t*)&sU[base];
                a[mt][1] = *(const uint32_t*)&sU[base + 8 * 264];
                a[mt][2] = *(const uint32_t*)&sU[base + 8];
                a[mt][3] = *(const uint32_t*)&sU[base + 8 * 264 + 8];
            }
            #pragma unroll
            for (int nt = 0; nt < 4; ++nt) {
                int nb = (wc * 32 + nt * 8 + gid) * 40 + bk + tg * 2;
                uint32_t b0 = *(const uint32_t*)&sB[nb];
                uint32_t b1 = *(const uint32_t*)&sB[nb + 8];
                mma_bf16(c[0][nt], a[0], b0, b1);
                mma_bf16(c[1][nt], a[1], b0, b1);
            }
        }
    }

    // ============ epilogue 2: bias2 -> global ============
    #pragma unroll
    for (int mt = 0; mt < 2; ++mt) {
        #pragma unroll
        for (int nt = 0; nt < 4; ++nt) {
            int col = wc * 32 + nt * 8 + tg * 2;
            float bx = bias2[col], by = bias2[col + 1];
            int r0 = brow + wr * 32 + mt * 16 + gid;
            float v0 = c[mt][nt][0] + bx, v1 = c[mt][nt][1] + by;
            float v2 = c[mt][nt][2] + bx, v3 = c[mt][nt][3] + by;
            if (r0 < M)     *(float2*)(Cout + (size_t)r0 * D + col)       = make_float2(v0, v1);
            if (r0 + 8 < M) *(float2*)(Cout + (size_t)(r0 + 8) * D + col) = make_float2(v2, v3);
        }
    }
}

// ---------------- final GEMM via mma.sync: C = concat(A0..A3) @ W + bias ----
__global__ void __launch_bounds__(256) k_gemm_final(
    const float* __restrict__ A0, const float* __restrict__ A1,
    const float* __restrict__ A2, const float* __restrict__ A3,
    int wbase, const float* __restrict__ bias, float* __restrict__ C, int M)
{
    __shared__ __align__(16) __nv_bfloat16 sA[128 * 40];
    __shared__ __align__(16) __nv_bfloat16 sB[128 * 40];

    const int tid  = threadIdx.x;
    const int w    = tid >> 5;
    const int lane = tid & 31;
    const int wr   = w & 3;
    const int wc   = w >> 2;
    const int gid  = lane >> 2;
    const int tg   = lane & 3;
    const int brow = blockIdx.x * 128;

    const float* srcs[4] = {A0, A1, A2, A3};

    float c[2][8][4];
    #pragma unroll
    for (int mt = 0; mt < 2; ++mt)
        #pragma unroll
        for (int nt = 0; nt < 8; ++nt)
            #pragma unroll
            for (int j = 0; j < 4; ++j) c[mt][nt][j] = 0.f;

    const int arow  = tid >> 1;
    const int ahalf = tid & 1;
    const int grow  = brow + arow;

    for (int ch = 0; ch < 32; ++ch) {
        if (ch) __syncthreads();
        {
            const uint4* wsrc = (const uint4*)g_wb[wbase + ch];
            uint4* bd = (uint4*)sB;
            #pragma unroll
            for (int i = 0; i < 3; ++i) {
                int t = tid + 256 * i;
                if (t < 640) bd[t] = wsrc[t];
            }
        }
        {
            float v[8];
            if (grow < M) {
                const float* ap = srcs[ch >> 3] + (size_t)grow * D + (ch & 7) * 16 + ahalf * 8;
                float4 f0 = *(const float4*)(ap);
                float4 f1 = *(const float4*)(ap + 4);
                v[0] = f0.x; v[1] = f0.y; v[2] = f0.z; v[3] = f0.w;
                v[4] = f1.x; v[5] = f1.y; v[6] = f1.z; v[7] = f1.w;
            } else {
                #pragma unroll
                for (int i = 0; i < 8; ++i) v[i] = 0.f;
            }
            uint32_t hw[4], lw_[4];
            #pragma unroll
            for (int q = 0; q < 4; ++q) {
                __nv_bfloat16 h0, l0, h1, l1;
                split_bf16(v[q * 2],     h0, l0);
                split_bf16(v[q * 2 + 1], h1, l1);
                __nv_bfloat162 hp = {h0, h1}, lp = {l0, l1};
                hw[q]  = *(uint32_t*)&hp;
                lw_[q] = *(uint32_t*)&lp;
            }
            *(uint4*)&sA[arow * 40 + ahalf * 8]      = *(uint4*)hw;
            *(uint4*)&sA[arow * 40 + 16 + ahalf * 8] = *(uint4*)lw_;
        }
        __syncthreads();

        #pragma unroll
        for (int p = 0; p < 3; ++p) {
            const int ak = (p == 1) ? 16 : 0;
            const int bk = (p == 2) ? 16 : 0;
            uint32_t a[2][4];
            #pragma unroll
            for (int mt = 0; mt < 2; ++mt) {
                int base = (wr * 32 + mt * 16 + gid) * 40 + ak + tg * 2;
                a[mt][0] = *(const uint32_t*)&sA[base];
                a[mt][1] = *(const uint32_t*)&sA[base + 8 * 40];
                a[mt][2] = *(const uint32_t*)&sA[base + 8];
                a[mt][3] = *(const uint32_t*)&sA[base + 8 * 40 + 8];
            }
            #pragma unroll
            for (int nt = 0; nt < 8; ++nt) {
                int nb = (wc * 64 + nt * 8 + gid) * 40 + bk + tg * 2;
                uint32_t b0 = *(const uint32_t*)&sB[nb];
                uint32_t b1 = *(const uint32_t*)&sB[nb + 8];
                mma_bf16(c[0][nt], a[0], b0, b1);
                mma_bf16(c[1][nt], a[1], b0, b1);
            }
        }
    }

    #pragma unroll
    for (int mt = 0; mt < 2; ++mt) {
        #pragma unroll
        for (int nt = 0; nt < 8; ++nt) {
            int col  = wc * 64 + nt * 8 + tg * 2;
            float bx = bias[col], by = bias[col + 1];
            int r0 = brow + wr * 32 + mt * 16 + gid;
            float v0 = c[mt][nt][0] + bx, v1 = c[mt][nt][1] + by;
            float v2 = c[mt][nt][2] + bx, v3 = c[mt][nt][3] + by;
            if (r0 < M)     *(float2*)(C + (size_t)r0 * D + col)       = make_float2(v0, v1);
            if (r0 + 8 < M) *(float2*)(C + (size_t)(r0 + 8) * D + col) = make_float2(v2, v3);
        }
    }
}

// ---------------- launcher ----------------
extern "C" void kernel_launch(void* const* d_in, const int* in_sizes, int n_in,
                              void* d_out, int out_size) {
    const float* x   = (const float*)d_in[0];
    const int*   ei  = (const int*)  d_in[1];
    const float* ea  = (const float*)d_in[2];
    const float* lw  = (const float*)d_in[3];
    const float* lb  = (const float*)d_in[4];
    const float* eps = (const float*)d_in[5];
    const float* w1  = (const float*)d_in[6];
    const float* b1  = (const float*)d_in[7];
    const float* w2  = (const float*)d_in[8];
    const float* b2  = (const float*)d_in[9];
    const float* fw  = (const float*)d_in[10];
    const float* fb  = (const float*)d_in[11];
    float* out = (float*)d_out;

    const int N = in_sizes[0] / D;
    const int E = in_sizes[2];

    float *hbuf, *tmp;
    cudaGetSymbolAddress((void**)&hbuf, g_h);
    cudaGetSymbolAddress((void**)&tmp,  g_tmp);

    // weight prep + CSR build
    k_wprep<<<(80 * 128 * 16 + 255) / 256, 256>>>(w1, w2, fw);
    k_zero<<<(N + 255) / 256, 256>>>(N);
    k_hist<<<(E + 255) / 256, 256>>>(ei + E, E);
    const int nb = (N + 1023) / 1024;
    k_scan1<<<nb, 1024>>>(N);
    k_scan2<<<1, 32>>>(nb);
    k_scan3<<<nb, 1024>>>(N);
    k_scatter<<<(E + 255) / 256, 256>>>(ei, ei + E, ea, E);

    const float* h = x;
    for (int l = 0; l < 3; ++l) {
        float* hl = hbuf + (size_t)l * NMAX * D;
        k_agg<<<(N + 7) / 8, 256>>>(h, lw + l * D, lb + l * D, eps, l, tmp, N);
        k_layer_mlp<<<(N + 63) / 64, 256>>>(tmp, (l * 2 + 0) * 8, (l * 2 + 1) * 8,
                                            b1 + l * D, b2 + l * D, hl, N);
        h = hl;
    }

    // final: [x | h1 | h2 | h3] @ fw + fb
    k_gemm_final<<<(N + 127) / 128, 256>>>(x, hbuf, hbuf + (size_t)NMAX * D,
                                           hbuf + (size_t)2 * NMAX * D, 48, fb, out, N);
}

// round 7
// speedup vs baseline: 1.7586x; 1.0022x over previous
#include <cuda_runtime.h>
#include <cuda_bf16.h>
#include <cstdint>

#define NMAX 50000
#define EMAX 800000
#define D 128

// ---------------- device scratch (no allocations allowed) ----------------
__device__ int   g_cnt[NMAX];
__device__ int   g_off[NMAX + 1];
__device__ int   g_cur[NMAX];
__device__ int2  g_edge[EMAX];       // {src, attr-bits}
__device__ int   g_bsum[64];
__device__ int   g_bpre[64];
__device__ float g_h[3][NMAX * D];   // h1, h2, h3
__device__ float g_tmp[NMAX * D];
// prepacked weight chunks: 80 chunks (6 layer-GEMMs x 8 + final x 32).
// chunk = 128 n-rows x 40 bf16 (k 0..15 = hi, k 16..31 = lo, 32..39 pad).
__device__ __align__(16) __nv_bfloat16 g_wb[80][128 * 40];

// ---------------- preprocessing: CSR by target via counting sort ----------------
__global__ void k_zero(int n) {
    int i = blockIdx.x * blockDim.x + threadIdx.x;
    if (i < n) g_cnt[i] = 0;
}

__global__ void k_hist(const int* __restrict__ tgt, int E) {
    int i = blockIdx.x * blockDim.x + threadIdx.x;
    if (i < E) atomicAdd(&g_cnt[tgt[i]], 1);
}

__device__ __forceinline__ int block_scan_incl(int v) {
    __shared__ int wsum[32];
    const int lane = threadIdx.x & 31;
    const int wid  = threadIdx.x >> 5;
    int s = v;
    #pragma unroll
    for (int d = 1; d < 32; d <<= 1) {
        int t = __shfl_up_sync(0xFFFFFFFFu, s, d);
        if (lane >= d) s += t;
    }
    if (lane == 31) wsum[wid] = s;
    __syncthreads();
    if (wid == 0) {
        int ws = wsum[lane];
        #pragma unroll
        for (int d = 1; d < 32; d <<= 1) {
            int t = __shfl_up_sync(0xFFFFFFFFu, ws, d);
            if (lane >= d) ws += t;
        }
        wsum[lane] = ws;
    }
    __syncthreads();
    return s + (wid ? wsum[wid - 1] : 0);
}

__global__ void k_scan1(int n) {
    int i = blockIdx.x * 1024 + threadIdx.x;
    int v = (i < n) ? g_cnt[i] : 0;
    int incl = block_scan_incl(v);
    if (i < n) g_off[i + 1] = incl;
    if (threadIdx.x == 1023) g_bsum[blockIdx.x] = incl;
}

__global__ void k_scan2(int nb) {
    int lane = threadIdx.x;           // 32 threads
    int v0 = (lane      < nb) ? g_bsum[lane]      : 0;
    int v1 = (lane + 32 < nb) ? g_bsum[lane + 32] : 0;
    int s = v0;
    #pragma unroll
    for (int d = 1; d < 32; d <<= 1) {
        int t = __shfl_up_sync(0xFFFFFFFFu, s, d);
        if (lane >= d) s += t;
    }
    int tot0 = __shfl_sync(0xFFFFFFFFu, s, 31);
    int s1 = v1;
    #pragma unroll
    for (int d = 1; d < 32; d <<= 1) {
        int t = __shfl_up_sync(0xFFFFFFFFu, s1, d);
        if (lane >= d) s1 += t;
    }
    if (lane < nb)      g_bpre[lane]      = s - v0;
    if (lane + 32 < nb) g_bpre[lane + 32] = tot0 + s1 - v1;
}

__global__ void k_scan3(int n) {
    int i = blockIdx.x * 1024 + threadIdx.x;
    if (i < n) {
        int off = g_off[i + 1] + g_bpre[blockIdx.x];
        g_off[i + 1] = off;
        g_cur[i]     = off - g_cnt[i];
    }
    if (i == 0) g_off[0] = 0;
}

__global__ void k_scatter(const int* __restrict__ src, const int* __restrict__ tgt,
                          const float* __restrict__ ea, int E) {
    int i = blockIdx.x * blockDim.x + threadIdx.x;
    if (i < E) {
        int p = atomicAdd(&g_cur[tgt[i]], 1);
        g_edge[p] = make_int2(src[i], __float_as_int(ea[i]));
    }
}

// ---------------- aggregation: one warp per node ----------------
__global__ void k_agg(const float* __restrict__ h,
                      const float* __restrict__ lw, const float* __restrict__ lb,
                      const float* __restrict__ eps, int l,
                      float* __restrict__ out, int n) {
    int warp = (blockIdx.x * blockDim.x + threadIdx.x) >> 5;
    int lane = threadIdx.x & 31;
    if (warp >= n) return;
    int s0 = g_off[warp], s1 = g_off[warp + 1];
    float4 lw4 = *(const float4*)(lw + lane * 4);
    float4 lb4 = *(const float4*)(lb + lane * 4);
    float4 acc = make_float4(0.f, 0.f, 0.f, 0.f);
    #pragma unroll 4
    for (int e = s0; e < s1; ++e) {
        int2  p = g_edge[e];
        float a = __int_as_float(p.y);
        float4 hv = *(const float4*)(h + (size_t)p.x * D + lane * 4);
        acc.x += fmaxf(fmaf(a, lw4.x, lb4.x) + hv.x, 0.f);
        acc.y += fmaxf(fmaf(a, lw4.y, lb4.y) + hv.y, 0.f);
        acc.z += fmaxf(fmaf(a, lw4.z, lb4.z) + hv.z, 0.f);
        acc.w += fmaxf(fmaf(a, lw4.w, lb4.w) + hv.w, 0.f);
    }
    float inv = 1.f / (float)(s1 - s0);
    float g   = 1.f + eps[l];
    float4 hn = *(const float4*)(h + (size_t)warp * D + lane * 4);
    float4 o;
    o.x = acc.x * inv + g * hn.x;
    o.y = acc.y * inv + g * hn.y;
    o.z = acc.z * inv + g * hn.z;
    o.w = acc.w * inv + g * hn.w;
    *(float4*)(out + (size_t)warp * D + lane * 4) = o;
}

// ---------------- weight prep: transpose + bf16 split into g_wb ----------------
__global__ void k_wprep(const float* __restrict__ w1, const float* __restrict__ w2,
                        const float* __restrict__ fw) {
    int idx = blockIdx.x * blockDim.x + threadIdx.x;     // 80 * 128 * 16 = 163840
    if (idx >= 80 * 128 * 16) return;
    int ch  = idx >> 11;
    int rem = idx & 2047;
    int n   = rem >> 4;
    int kk  = rem & 15;
    const float* W;
    int kg;
    if (ch < 48) {
        int g  = ch >> 3;
        int cw = ch & 7;
        int layer = g >> 1;
        W  = (g & 1) ? (w2 + (size_t)layer * D * D) : (w1 + (size_t)layer * D * D);
        kg = cw * 16 + kk;
    } else {
        int cw = ch - 48;
        W  = fw;
        kg = cw * 16 + kk;
    }
    float v = W[(size_t)kg * 128 + n];
    __nv_bfloat16 hi = __float2bfloat16(v);
    __nv_bfloat16 lo = __float2bfloat16(v - __bfloat162float(hi));
    g_wb[ch][n * 40 + kk]      = hi;
    g_wb[ch][n * 40 + 16 + kk] = lo;
}

// ---------------- HMMA / LDSM helpers ----------------
__device__ __forceinline__ void mma_bf16(float* c, const uint32_t* a, uint32_t b0, uint32_t b1) {
    asm volatile(
        "mma.sync.aligned.m16n8k16.row.col.f32.bf16.bf16.f32 "
        "{%0,%1,%2,%3}, {%4,%5,%6,%7}, {%8,%9}, {%0,%1,%2,%3};"
        : "+f"(c[0]), "+f"(c[1]), "+f"(c[2]), "+f"(c[3])
        : "r"(a[0]), "r"(a[1]), "r"(a[2]), "r"(a[3]), "r"(b0), "r"(b1));
}

__device__ __forceinline__ void ldsm_x4(uint32_t* r, uint32_t addr) {
    asm volatile("ldmatrix.sync.aligned.m8n8.x4.shared.b16 {%0,%1,%2,%3}, [%4];"
                 : "=r"(r[0]), "=r"(r[1]), "=r"(r[2]), "=r"(r[3]) : "r"(addr));
}

__device__ __forceinline__ void split_bf16(float v, __nv_bfloat16& hi, __nv_bfloat16& lo) {
    hi = __float2bfloat16(v);
    lo = __float2bfloat16(v - __bfloat162float(hi));
}

// ---------------- fused layer MLP: h = relu(A@w1+b1)@w2+b2 ----------------
// 64x128 tile per 256-thread CTA. 8 warps: wr = w&1 (32 rows), wc = w>>1 (32 cols).
// sU aliases: phase-1 A staging (64x40) then sMid (64x264: cols 0..127 hi, 128..255 lo).
__global__ void __launch_bounds__(256) k_layer_mlp(
    const float* __restrict__ A, int wb1, int wb2,
    const float* __restrict__ bias1, const float* __restrict__ bias2,
    float* __restrict__ Cout, int M)
{
    __shared__ __align__(16) __nv_bfloat16 sU[64 * 264];
    __shared__ __align__(16) __nv_bfloat16 sB[128 * 40];

    const int tid  = threadIdx.x;
    const int w    = tid >> 5;
    const int lane = tid & 31;
    const int wr   = w & 1;
    const int wc   = w >> 1;
    const int gid  = lane >> 2;
    const int tg   = lane & 3;
    const int lg   = lane >> 3;      // ldmatrix group 0..3
    const int lr   = lane & 7;
    const int brow = blockIdx.x * 64;

    const uint32_t sUb = (uint32_t)__cvta_generic_to_shared(sU);
    const uint32_t sBb = (uint32_t)__cvta_generic_to_shared(sB);

    // ldmatrix lane offsets (elements):
    // A frag: row = R + (lg&1)*8 + lr, k = ak + (lg>>1)*8
    const int a_row_off = (lg & 1) * 8 + lr;
    const int a_k_off   = (lg >> 1) * 8;
    // B frag: n = CB + (lg>>1)*8 + lr, k = bk + (lg&1)*8
    const int b_n_off   = (lg >> 1) * 8 + lr;
    const int b_k_off   = (lg & 1) * 8;

    float c[2][4][4];
    #pragma unroll
    for (int mt = 0; mt < 2; ++mt)
        #pragma unroll
        for (int nt = 0; nt < 4; ++nt)
            #pragma unroll
            for (int j = 0; j < 4; ++j) c[mt][nt][j] = 0.f;

    const int arow = tid >> 2;       // 0..63
    const int aq   = tid & 3;        // 4 fp32 each
    const int grow = brow + arow;

    // ================= phase 1: mid = A @ w1 =================
    for (int ch = 0; ch < 8; ++ch) {
        if (ch) __syncthreads();
        {   // stage B chunk
            const uint4* wsrc = (const uint4*)g_wb[wb1 + ch];
            uint4* bd = (uint4*)sB;
            #pragma unroll
            for (int i = 0; i < 3; ++i) {
                int t = tid + 256 * i;
                if (t < 640) bd[t] = wsrc[t];
            }
        }
        {   // stage A: 4 fp32 -> bf16 hi/lo
            float v[4];
            if (grow < M) {
                float4 f = *(const float4*)(A + (size_t)grow * D + ch * 16 + aq * 4);
                v[0] = f.x; v[1] = f.y; v[2] = f.z; v[3] = f.w;
            } else {
                v[0] = v[1] = v[2] = v[3] = 0.f;
            }
            uint32_t hw[2], lw_[2];
            #pragma unroll
            for (int q = 0; q < 2; ++q) {
                __nv_bfloat16 h0, l0, h1, l1;
                split_bf16(v[q * 2],     h0, l0);
                split_bf16(v[q * 2 + 1], h1, l1);
                __nv_bfloat162 hp = {h0, h1}, lp = {l0, l1};
                hw[q]  = *(uint32_t*)&hp;
                lw_[q] = *(uint32_t*)&lp;
            }
            *(uint2*)&sU[arow * 40 + aq * 4]      = *(uint2*)hw;
            *(uint2*)&sU[arow * 40 + 16 + aq * 4] = *(uint2*)lw_;
        }
        __syncthreads();

        #pragma unroll
        for (int p = 0; p < 3; ++p) {
            const int ak = (p == 1) ? 16 : 0;
            const int bk = (p == 2) ? 16 : 0;
            uint32_t a[2][4], b[2][4];
            #pragma unroll
            for (int mt = 0; mt < 2; ++mt)
                ldsm_x4(a[mt], sUb + ((wr * 32 + mt * 16 + a_row_off) * 40 + ak + a_k_off) * 2);
            #pragma unroll
            for (int np = 0; np < 2; ++np)
                ldsm_x4(b[np], sBb + ((wc * 32 + np * 16 + b_n_off) * 40 + bk + b_k_off) * 2);
            #pragma unroll
            for (int np = 0; np < 2; ++np) {
                mma_bf16(c[0][np * 2],     a[0], b[np][0], b[np][1]);
                mma_bf16(c[1][np * 2],     a[1], b[np][0], b[np][1]);
                mma_bf16(c[0][np * 2 + 1], a[0], b[np][2], b[np][3]);
                mma_bf16(c[1][np * 2 + 1], a[1], b[np][2], b[np][3]);
            }
        }
    }
    __syncthreads();   // staging region dead; safe to overwrite as sMid

    // ============ epilogue 1: bias + relu + bf16 split -> sMid ============
    #pragma unroll
    for (int mt = 0; mt < 2; ++mt) {
        #pragma unroll
        for (int nt = 0; nt < 4; ++nt) {
            int col = wc * 32 + nt * 8 + tg * 2;
            float bx = bias1[col], by = bias1[col + 1];
            #pragma unroll
            for (int half = 0; half < 2; ++half) {
                int r = wr * 32 + mt * 16 + gid + half * 8;
                float v0 = fmaxf(c[mt][nt][half * 2]     + bx, 0.f);
                float v1 = fmaxf(c[mt][nt][half * 2 + 1] + by, 0.f);
                __nv_bfloat16 h0, l0, h1, l1;
                split_bf16(v0, h0, l0);
                split_bf16(v1, h1, l1);
                __nv_bfloat162 hp = {h0, h1}, lp = {l0, l1};
                *(uint32_t*)&sU[r * 264 + col]       = *(uint32_t*)&hp;
                *(uint32_t*)&sU[r * 264 + 128 + col] = *(uint32_t*)&lp;
            }
        }
    }
    __syncthreads();

    // ================= phase 2: h = mid @ w2 =================
    #pragma unroll
    for (int mt = 0; mt < 2; ++mt)
        #pragma unroll
        for (int nt = 0; nt < 4; ++nt)
            #pragma unroll
            for (int j = 0; j < 4; ++j) c[mt][nt][j] = 0.f;

    for (int ch = 0; ch < 8; ++ch) {
        if (ch) __syncthreads();
        {
            const uint4* wsrc = (const uint4*)g_wb[wb2 + ch];
            uint4* bd = (uint4*)sB;
            #pragma unroll
            for (int i = 0; i < 3; ++i) {
                int t = tid + 256 * i;
                if (t < 640) bd[t] = wsrc[t];
            }
        }
        __syncthreads();

        #pragma unroll
        for (int p = 0; p < 3; ++p) {
            const int ak = ch * 16 + ((p == 1) ? 128 : 0);
            const int bk = (p == 2) ? 16 : 0;
            uint32_t a[2][4], b[2][4];
            #pragma unroll
            for (int mt = 0; mt < 2; ++mt)
                ldsm_x4(a[mt], sUb + ((wr * 32 + mt * 16 + a_row_off) * 264 + ak + a_k_off) * 2);
            #pragma unroll
            for (int np = 0; np < 2; ++np)
                ldsm_x4(b[np], sBb + ((wc * 32 + np * 16 + b_n_off) * 40 + bk + b_k_off) * 2);
            #pragma unroll
            for (int np = 0; np < 2; ++np) {
                mma_bf16(c[0][np * 2],     a[0], b[np][0], b[np][1]);
                mma_bf16(c[1][np * 2],     a[1], b[np][0], b[np][1]);
                mma_bf16(c[0][np * 2 + 1], a[0], b[np][2], b[np][3]);
                mma_bf16(c[1][np * 2 + 1], a[1], b[np][2], b[np][3]);
            }
        }
    }

    // ============ epilogue 2: bias2 -> global ============
    #pragma unroll
    for (int mt = 0; mt < 2; ++mt) {
        #pragma unroll
        for (int nt = 0; nt < 4; ++nt) {
            int col = wc * 32 + nt * 8 + tg * 2;
            float bx = bias2[col], by = bias2[col + 1];
            int r0 = brow + wr * 32 + mt * 16 + gid;
            float v0 = c[mt][nt][0] + bx, v1 = c[mt][nt][1] + by;
            float v2 = c[mt][nt][2] + bx, v3 = c[mt][nt][3] + by;
            if (r0 < M)     *(float2*)(Cout + (size_t)r0 * D + col)       = make_float2(v0, v1);
            if (r0 + 8 < M) *(float2*)(Cout + (size_t)(r0 + 8) * D + col) = make_float2(v2, v3);
        }
    }
}

// ---------------- final GEMM via mma.sync: C = concat(A0..A3) @ W + bias ----
__global__ void __launch_bounds__(256) k_gemm_final(
    const float* __restrict__ A0, const float* __restrict__ A1,
    const float* __restrict__ A2, const float* __restrict__ A3,
    int wbase, const float* __restrict__ bias, float* __restrict__ C, int M)
{
    __shared__ __align__(16) __nv_bfloat16 sA[128 * 40];
    __shared__ __align__(16) __nv_bfloat16 sB[128 * 40];

    const int tid  = threadIdx.x;
    const int w    = tid >> 5;
    const int lane = tid & 31;
    const int wr   = w & 3;
    const int wc   = w >> 2;
    const int gid  = lane >> 2;
    const int tg   = lane & 3;
    const int lg   = lane >> 3;
    const int lr   = lane & 7;
    const int brow = blockIdx.x * 128;

    const uint32_t sAb = (uint32_t)__cvta_generic_to_shared(sA);
    const uint32_t sBb = (uint32_t)__cvta_generic_to_shared(sB);

    const int a_row_off = (lg & 1) * 8 + lr;
    const int a_k_off   = (lg >> 1) * 8;
    const int b_n_off   = (lg >> 1) * 8 + lr;
    const int b_k_off   = (lg & 1) * 8;

    const float* srcs[4] = {A0, A1, A2, A3};

    float c[2][8][4];
    #pragma unroll
    for (int mt = 0; mt < 2; ++mt)
        #pragma unroll
        for (int nt = 0; nt < 8; ++nt)
            #pragma unroll
            for (int j = 0; j < 4; ++j) c[mt][nt][j] = 0.f;

    const int arow  = tid >> 1;
    const int ahalf = tid & 1;
    const int grow  = brow + arow;

    for (int ch = 0; ch < 32; ++ch) {
        if (ch) __syncthreads();
        {
            const uint4* wsrc = (const uint4*)g_wb[wbase + ch];
            uint4* bd = (uint4*)sB;
            #pragma unroll
            for (int i = 0; i < 3; ++i) {
                int t = tid + 256 * i;
                if (t < 640) bd[t] = wsrc[t];
            }
        }
        {
            float v[8];
            if (grow < M) {
                const float* ap = srcs[ch >> 3] + (size_t)grow * D + (ch & 7) * 16 + ahalf * 8;
                float4 f0 = *(const float4*)(ap);
                float4 f1 = *(const float4*)(ap + 4);
                v[0] = f0.x; v[1] = f0.y; v[2] = f0.z; v[3] = f0.w;
                v[4] = f1.x; v[5] = f1.y; v[6] = f1.z; v[7] = f1.w;
            } else {
                #pragma unroll
                for (int i = 0; i < 8; ++i) v[i] = 0.f;
            }
            uint32_t hw[4], lw_[4];
            #pragma unroll
            for (int q = 0; q < 4; ++q) {
                __nv_bfloat16 h0, l0, h1, l1;
                split_bf16(v[q * 2],     h0, l0);
                split_bf16(v[q * 2 + 1], h1, l1);
                __nv_bfloat162 hp = {h0, h1}, lp = {l0, l1};
                hw[q]  = *(uint32_t*)&hp;
                lw_[q] = *(uint32_t*)&lp;
            }
            *(uint4*)&sA[arow * 40 + ahalf * 8]      = *(uint4*)hw;
            *(uint4*)&sA[arow * 40 + 16 + ahalf * 8] = *(uint4*)lw_;
        }
        __syncthreads();

        #pragma unroll
        for (int p = 0; p < 3; ++p) {
            const int ak = (p == 1) ? 16 : 0;
            const int bk = (p == 2) ? 16 : 0;
            uint32_t a[2][4], b[4][4];
            #pragma unroll
            for (int mt = 0; mt < 2; ++mt)
                ldsm_x4(a[mt], sAb + ((wr * 32 + mt * 16 + a_row_off) * 40 + ak + a_k_off) * 2);
            #pragma unroll
            for (int np = 0; np < 4; ++np)
                ldsm_x4(b[np], sBb + ((wc * 64 + np * 16 + b_n_off) * 40 + bk + b_k_off) * 2);
            #pragma unroll
            for (int np = 0; np < 4; ++np) {
                mma_bf16(c[0][np * 2],     a[0], b[np][0], b[np][1]);
                mma_bf16(c[1][np * 2],     a[1], b[np][0], b[np][1]);
                mma_bf16(c[0][np * 2 + 1], a[0], b[np][2], b[np][3]);
                mma_bf16(c[1][np * 2 + 1], a[1], b[np][2], b[np][3]);
            }
        }
    }

    #pragma unroll
    for (int mt = 0; mt < 2; ++mt) {
        #pragma unroll
        for (int nt = 0; nt < 8; ++nt) {
            int col  = wc * 64 + nt * 8 + tg * 2;
            float bx = bias[col], by = bias[col + 1];
            int r0 = brow + wr * 32 + mt * 16 + gid;
            float v0 = c[mt][nt][0] + bx, v1 = c[mt][nt][1] + by;
            float v2 = c[mt][nt][2] + bx, v3 = c[mt][nt][3] + by;
            if (r0 < M)     *(float2*)(C + (size_t)r0 * D + col)       = make_float2(v0, v1);
            if (r0 + 8 < M) *(float2*)(C + (size_t)(r0 + 8) * D + col) = make_float2(v2, v3);
        }
    }
}

// ---------------- launcher ----------------
extern "C" void kernel_launch(void* const* d_in, const int* in_sizes, int n_in,
                              void* d_out, int out_size) {
    const float* x   = (const float*)d_in[0];
    const int*   ei  = (const int*)  d_in[1];
    const float* ea  = (const float*)d_in[2];
    const float* lw  = (const float*)d_in[3];
    const float* lb  = (const float*)d_in[4];
    const float* eps = (const float*)d_in[5];
    const float* w1  = (const float*)d_in[6];
    const float* b1  = (const float*)d_in[7];
    const float* w2  = (const float*)d_in[8];
    const float* b2  = (const float*)d_in[9];
    const float* fw  = (const float*)d_in[10];
    const float* fb  = (const float*)d_in[11];
    float* out = (float*)d_out;

    const int N = in_sizes[0] / D;
    const int E = in_sizes[2];

    float *hbuf, *tmp;
    cudaGetSymbolAddress((void**)&hbuf, g_h);
    cudaGetSymbolAddress((void**)&tmp,  g_tmp);

    // weight prep + CSR build
    k_wprep<<<(80 * 128 * 16 + 255) / 256, 256>>>(w1, w2, fw);
    k_zero<<<(N + 255) / 256, 256>>>(N);
    k_hist<<<(E + 255) / 256, 256>>>(ei + E, E);
    const int nb = (N + 1023) / 1024;
    k_scan1<<<nb, 1024>>>(N);
    k_scan2<<<1, 32>>>(nb);
    k_scan3<<<nb, 1024>>>(N);
    k_scatter<<<(E + 255) / 256, 256>>>(ei, ei + E, ea, E);

    const float* h = x;
    for (int l = 0; l < 3; ++l) {
        float* hl = hbuf + (size_t)l * NMAX * D;
        k_agg<<<(N + 7) / 8, 256>>>(h, lw + l * D, lb + l * D, eps, l, tmp, N);
        k_layer_mlp<<<(N + 63) / 64, 256>>>(tmp, (l * 2 + 0) * 8, (l * 2 + 1) * 8,
                                            b1 + l * D, b2 + l * D, hl, N);
        h = hl;
    }

    // final: [x | h1 | h2 | h3] @ fw + fb
    k_gemm_final<<<(N + 127) / 128, 256>>>(x, hbuf, hbuf + (size_t)NMAX * D,
                                           hbuf + (size_t)2 * NMAX * D, 48, fb, out, N);
}

// round 8
// speedup vs baseline: 2.1240x; 1.2078x over previous
#include <cuda_runtime.h>
#include <cuda_bf16.h>
#include <cstdint>

#define NMAX 50000
#define EMAX 800000
#define D 128

// ---------------- device scratch (no allocations allowed) ----------------
__device__ int   g_cnt[NMAX];
__device__ int   g_off[NMAX + 1];
__device__ int   g_cur[NMAX];
__device__ int2  g_edge[EMAX];       // {src, attr-bits}
__device__ int   g_bsum[64];
__device__ int   g_bpre[64];
__device__ float g_h[3][NMAX * D];   // h1, h2, h3
__device__ float g_tmp[NMAX * D];
// prepacked weight chunks: 40 chunks (6 layer-GEMMs x 4 + final x 16), KB=32.
// chunk = 128 n-rows x 72 bf16 (k 0..31 = hi, 32..63 = lo, 64..71 pad).
__device__ __align__(16) __nv_bfloat16 g_wb[40][128 * 72];

// ---------------- preprocessing: CSR by target via counting sort ----------------
__global__ void k_zero(int n) {
    int i = blockIdx.x * blockDim.x + threadIdx.x;
    if (i < n) g_cnt[i] = 0;
}

__global__ void k_hist(const int* __restrict__ tgt, int E) {
    int i = blockIdx.x * blockDim.x + threadIdx.x;
    if (i < E) atomicAdd(&g_cnt[tgt[i]], 1);
}

__device__ __forceinline__ int block_scan_incl(int v) {
    __shared__ int wsum[32];
    const int lane = threadIdx.x & 31;
    const int wid  = threadIdx.x >> 5;
    int s = v;
    #pragma unroll
    for (int d = 1; d < 32; d <<= 1) {
        int t = __shfl_up_sync(0xFFFFFFFFu, s, d);
        if (lane >= d) s += t;
    }
    if (lane == 31) wsum[wid] = s;
    __syncthreads();
    if (wid == 0) {
        int ws = wsum[lane];
        #pragma unroll
        for (int d = 1; d < 32; d <<= 1) {
            int t = __shfl_up_sync(0xFFFFFFFFu, ws, d);
            if (lane >= d) ws += t;
        }
        wsum[lane] = ws;
    }
    __syncthreads();
    return s + (wid ? wsum[wid - 1] : 0);
}

__global__ void k_scan1(int n) {
    int i = blockIdx.x * 1024 + threadIdx.x;
    int v = (i < n) ? g_cnt[i] : 0;
    int incl = block_scan_incl(v);
    if (i < n) g_off[i + 1] = incl;
    if (threadIdx.x == 1023) g_bsum[blockIdx.x] = incl;
}

__global__ void k_scan2(int nb) {
    int lane = threadIdx.x;           // 32 threads
    int v0 = (lane      < nb) ? g_bsum[lane]      : 0;
    int v1 = (lane + 32 < nb) ? g_bsum[lane + 32] : 0;
    int s = v0;
    #pragma unroll
    for (int d = 1; d < 32; d <<= 1) {
        int t = __shfl_up_sync(0xFFFFFFFFu, s, d);
        if (lane >= d) s += t;
    }
    int tot0 = __shfl_sync(0xFFFFFFFFu, s, 31);
    int s1 = v1;
    #pragma unroll
    for (int d = 1; d < 32; d <<= 1) {
        int t = __shfl_up_sync(0xFFFFFFFFu, s1, d);
        if (lane >= d) s1 += t;
    }
    if (lane < nb)      g_bpre[lane]      = s - v0;
    if (lane + 32 < nb) g_bpre[lane + 32] = tot0 + s1 - v1;
}

__global__ void k_scan3(int n) {
    int i = blockIdx.x * 1024 + threadIdx.x;
    if (i < n) {
        int off = g_off[i + 1] + g_bpre[blockIdx.x];
        g_off[i + 1] = off;
        g_cur[i]     = off - g_cnt[i];
    }
    if (i == 0) g_off[0] = 0;
}

__global__ void k_scatter(const int* __restrict__ src, const int* __restrict__ tgt,
                          const float* __restrict__ ea, int E) {
    int i = blockIdx.x * blockDim.x + threadIdx.x;
    if (i < E) {
        int p = atomicAdd(&g_cur[tgt[i]], 1);
        g_edge[p] = make_int2(src[i], __float_as_int(ea[i]));
    }
}

// ---------------- aggregation: one warp per node ----------------
__global__ void k_agg(const float* __restrict__ h,
                      const float* __restrict__ lw, const float* __restrict__ lb,
                      const float* __restrict__ eps, int l,
                      float* __restrict__ out, int n) {
    int warp = (blockIdx.x * blockDim.x + threadIdx.x) >> 5;
    int lane = threadIdx.x & 31;
    if (warp >= n) return;
    int s0 = g_off[warp], s1 = g_off[warp + 1];
    float4 lw4 = *(const float4*)(lw + lane * 4);
    float4 lb4 = *(const float4*)(lb + lane * 4);
    float4 acc = make_float4(0.f, 0.f, 0.f, 0.f);
    #pragma unroll 4
    for (int e = s0; e < s1; ++e) {
        int2  p = g_edge[e];
        float a = __int_as_float(p.y);
        float4 hv = *(const float4*)(h + (size_t)p.x * D + lane * 4);
        acc.x += fmaxf(fmaf(a, lw4.x, lb4.x) + hv.x, 0.f);
        acc.y += fmaxf(fmaf(a, lw4.y, lb4.y) + hv.y, 0.f);
        acc.z += fmaxf(fmaf(a, lw4.z, lb4.z) + hv.z, 0.f);
        acc.w += fmaxf(fmaf(a, lw4.w, lb4.w) + hv.w, 0.f);
    }
    float inv = 1.f / (float)(s1 - s0);
    float g   = 1.f + eps[l];
    float4 hn = *(const float4*)(h + (size_t)warp * D + lane * 4);
    float4 o;
    o.x = acc.x * inv + g * hn.x;
    o.y = acc.y * inv + g * hn.y;
    o.z = acc.z * inv + g * hn.z;
    o.w = acc.w * inv + g * hn.w;
    *(float4*)(out + (size_t)warp * D + lane * 4) = o;
}

// ---------------- weight prep: transpose + bf16 split into g_wb ----------------
// 40 chunks (KB=32): ch<24 -> GEMM g=ch/4 (layer g/2, W = g&1 ? w2 : w1), cw=ch&3;
//                    ch>=24 -> final GEMM, cw=ch-24 (0..15).
__global__ void k_wprep(const float* __restrict__ w1, const float* __restrict__ w2,
                        const float* __restrict__ fw) {
    int idx = blockIdx.x * blockDim.x + threadIdx.x;     // 40 * 128 * 32 = 163840
    if (idx >= 40 * 128 * 32) return;
    int ch  = idx >> 12;
    int rem = idx & 4095;
    int n   = rem >> 5;
    int kk  = rem & 31;
    const float* W;
    int kg;
    if (ch < 24) {
        int g  = ch >> 2;
        int cw = ch & 3;
        int layer = g >> 1;
        W  = (g & 1) ? (w2 + (size_t)layer * D * D) : (w1 + (size_t)layer * D * D);
        kg = cw * 32 + kk;
    } else {
        int cw = ch - 24;
        W  = fw;
        kg = cw * 32 + kk;
    }
    float v = W[(size_t)kg * 128 + n];
    __nv_bfloat16 hi = __float2bfloat16(v);
    __nv_bfloat16 lo = __float2bfloat16(v - __bfloat162float(hi));
    g_wb[ch][n * 72 + kk]      = hi;
    g_wb[ch][n * 72 + 32 + kk] = lo;
}

// ---------------- HMMA / LDSM / cp.async helpers ----------------
__device__ __forceinline__ void mma_bf16(float* c, const uint32_t* a, uint32_t b0, uint32_t b1) {
    asm volatile(
        "mma.sync.aligned.m16n8k16.row.col.f32.bf16.bf16.f32 "
        "{%0,%1,%2,%3}, {%4,%5,%6,%7}, {%8,%9}, {%0,%1,%2,%3};"
        : "+f"(c[0]), "+f"(c[1]), "+f"(c[2]), "+f"(c[3])
        : "r"(a[0]), "r"(a[1]), "r"(a[2]), "r"(a[3]), "r"(b0), "r"(b1));
}

__device__ __forceinline__ void ldsm_x4(uint32_t* r, uint32_t addr) {
    asm volatile("ldmatrix.sync.aligned.m8n8.x4.shared.b16 {%0,%1,%2,%3}, [%4];"
                 : "=r"(r[0]), "=r"(r[1]), "=r"(r[2]), "=r"(r[3]) : "r"(addr));
}

__device__ __forceinline__ void cpasync16(uint32_t saddr, const void* gaddr) {
    asm volatile("cp.async.cg.shared.global [%0], [%1], 16;" :: "r"(saddr), "l"(gaddr));
}
__device__ __forceinline__ void cpasync_commit() { asm volatile("cp.async.commit_group;" ::: "memory"); }
__device__ __forceinline__ void cpasync_wait0()  { asm volatile("cp.async.wait_group 0;" ::: "memory"); }

__device__ __forceinline__ void split_bf16(float v, __nv_bfloat16& hi, __nv_bfloat16& lo) {
    hi = __float2bfloat16(v);
    lo = __float2bfloat16(v - __bfloat162float(hi));
}

// stage one 18432B weight chunk (1152 x 16B) via cp.async
__device__ __forceinline__ void stageB_async(uint32_t sbase, const __nv_bfloat16* src, int tid) {
    #pragma unroll
    for (int i = 0; i < 5; ++i) {
        int t = tid + 256 * i;
        if (t < 1152) cpasync16(sbase + t * 16, (const char*)src + t * 16);
    }
}

// pack 8 fp32 into hi/lo bf16 uint4s
__device__ __forceinline__ void pack8(const float* v, uint4& hiq, uint4& loq) {
    uint32_t hw[4], lw_[4];
    #pragma unroll
    for (int q = 0; q < 4; ++q) {
        __nv_bfloat16 h0, l0, h1, l1;
        split_bf16(v[q * 2],     h0, l0);
        split_bf16(v[q * 2 + 1], h1, l1);
        __nv_bfloat162 hp = {h0, h1}, lp = {l0, l1};
        hw[q]  = *(uint32_t*)&hp;
        lw_[q] = *(uint32_t*)&lp;
    }
    hiq = *(uint4*)hw;
    loq = *(uint4*)lw_;
}

#define SB_BUF_BYTES 18432
#define SA_LAYER_BYTES 9216
#define SMID_BYTES 33792

// ---------------- fused layer MLP: h = relu(A@w1+b1)@w2+b2 ----------------
// 64x128 tile / 256 threads. KB=32 pipelined: cp.async B + reg-prefetch A, double buffers.
__global__ void __launch_bounds__(256) k_layer_mlp(
    const float* __restrict__ A, int wb1, int wb2,
    const float* __restrict__ bias1, const float* __restrict__ bias2,
    float* __restrict__ Cout, int M)
{
    extern __shared__ __align__(16) char dyn[];
    __nv_bfloat16* sU = (__nv_bfloat16*)dyn;                       // sMid / phase-1 sA double buf
    __nv_bfloat16* sB = (__nv_bfloat16*)(dyn + SMID_BYTES);        // 2 x 9216 elems

    const int tid  = threadIdx.x;
    const int w    = tid >> 5;
    const int lane = tid & 31;
    const int wr   = w & 1;
    const int wc   = w >> 1;
    const int gid  = lane >> 2;
    const int tg   = lane & 3;
    const int lg   = lane >> 3;
    const int lr   = lane & 7;
    const int brow = blockIdx.x * 64;

    const uint32_t sUb = (uint32_t)__cvta_generic_to_shared(sU);
    const uint32_t sBb = (uint32_t)__cvta_generic_to_shared(sB);

    const int a_row_off = (lg & 1) * 8 + lr;
    const int a_k_off   = (lg >> 1) * 8;
    const int b_n_off   = (lg >> 1) * 8 + lr;
    const int b_k_off   = (lg & 1) * 8;

    float c[2][4][4];
    #pragma unroll
    for (int mt = 0; mt < 2; ++mt)
        #pragma unroll
        for (int nt = 0; nt < 4; ++nt)
            #pragma unroll
            for (int j = 0; j < 4; ++j) c[mt][nt][j] = 0.f;

    const int arow = tid >> 2;       // 0..63
    const int aq   = (tid & 3) * 8;  // 8 fp32 each
    const int grow = brow + arow;

    float v[8];
    // ---------- prologue: stage chunk 0 ----------
    stageB_async(sBb, g_wb[wb1], tid);
    cpasync_commit();
    if (grow < M) {
        float4 f0 = *(const float4*)(A + (size_t)grow * D + aq);
        float4 f1 = *(const float4*)(A + (size_t)grow * D + aq + 4);
        v[0]=f0.x; v[1]=f0.y; v[2]=f0.z; v[3]=f0.w; v[4]=f1.x; v[5]=f1.y; v[6]=f1.z; v[7]=f1.w;
    } else {
        #pragma unroll
        for (int i = 0; i < 8; ++i) v[i] = 0.f;
    }
    {
        uint4 hiq, loq; pack8(v, hiq, loq);
        *(uint4*)&sU[arow * 72 + aq]      = hiq;
        *(uint4*)&sU[arow * 72 + 32 + aq] = loq;
    }
    cpasync_wait0();
    __syncthreads();

    // ================= phase 1: mid = A @ w1 (4 chunks, pipelined) ============
    int buf = 0;
    for (int ch = 0; ch < 4; ++ch) {
        const bool more = (ch < 3);
        if (more) {
            stageB_async(sBb + (buf ^ 1) * SB_BUF_BYTES, g_wb[wb1 + ch + 1], tid);
            cpasync_commit();
            if (grow < M) {
                const float* ap = A + (size_t)grow * D + (ch + 1) * 32 + aq;
                float4 f0 = *(const float4*)(ap);
                float4 f1 = *(const float4*)(ap + 4);
                v[0]=f0.x; v[1]=f0.y; v[2]=f0.z; v[3]=f0.w; v[4]=f1.x; v[5]=f1.y; v[6]=f1.z; v[7]=f1.w;
            }
        }
        const uint32_t aB = sUb + buf * SA_LAYER_BYTES;
        const uint32_t bB = sBb + buf * SB_BUF_BYTES;
        #pragma unroll
        for (int ks = 0; ks < 2; ++ks) {
            #pragma unroll
            for (int p = 0; p < 3; ++p) {
                const int ak = ((p == 1) ? 32 : 0) + ks * 16;
                const int bk = ((p == 2) ? 32 : 0) + ks * 16;
                uint32_t a[2][4], b[2][4];
                #pragma unroll
                for (int mt = 0; mt < 2; ++mt)
                    ldsm_x4(a[mt], aB + ((wr * 32 + mt * 16 + a_row_off) * 72 + ak + a_k_off) * 2);
                #pragma unroll
                for (int np = 0; np < 2; ++np)
                    ldsm_x4(b[np], bB + ((wc * 32 + np * 16 + b_n_off) * 72 + bk + b_k_off) * 2);
                #pragma unroll
                for (int np = 0; np < 2; ++np) {
                    mma_bf16(c[0][np * 2],     a[0], b[np][0], b[np][1]);
                    mma_bf16(c[1][np * 2],     a[1], b[np][0], b[np][1]);
                    mma_bf16(c[0][np * 2 + 1], a[0], b[np][2], b[np][3]);
                    mma_bf16(c[1][np * 2 + 1], a[1], b[np][2], b[np][3]);
                }
            }
        }
        if (more) {
            uint4 hiq, loq; pack8(v, hiq, loq);
            __nv_bfloat16* sA1 = sU + (buf ^ 1) * (SA_LAYER_BYTES / 2);
            *(uint4*)&sA1[arow * 72 + aq]      = hiq;
            *(uint4*)&sA1[arow * 72 + 32 + aq] = loq;
        }
        cpasync_wait0();
        __syncthreads();
        buf ^= 1;
    }

    // ============ epilogue 1: bias + relu + bf16 split -> sMid ============
    #pragma unroll
    for (int mt = 0; mt < 2; ++mt) {
        #pragma unroll
        for (int nt = 0; nt < 4; ++nt) {
            int col = wc * 32 + nt * 8 + tg * 2;
            float bx = bias1[col], by = bias1[col + 1];
            #pragma unroll
            for (int half = 0; half < 2; ++half) {
                int r = wr * 32 + mt * 16 + gid + half * 8;
                float v0 = fmaxf(c[mt][nt][half * 2]     + bx, 0.f);
                float v1 = fmaxf(c[mt][nt][half * 2 + 1] + by, 0.f);
                __nv_bfloat16 h0, l0, h1, l1;
                split_bf16(v0, h0, l0);
                split_bf16(v1, h1, l1);
                __nv_bfloat162 hp = {h0, h1}, lp = {l0, l1};
                *(uint32_t*)&sU[r * 264 + col]       = *(uint32_t*)&hp;
                *(uint32_t*)&sU[r * 264 + 128 + col] = *(uint32_t*)&lp;
            }
        }
    }
    __syncthreads();

    // ================= phase 2: h = mid @ w2 (4 chunks, pipelined B) ============
    #pragma unroll
    for (int mt = 0; mt < 2; ++mt)
        #pragma unroll
        for (int nt = 0; nt < 4; ++nt)
            #pragma unroll
            for (int j = 0; j < 4; ++j) c[mt][nt][j] = 0.f;

    buf = 0;
    stageB_async(sBb, g_wb[wb2], tid);
    cpasync_commit();
    cpasync_wait0();
    __syncthreads();

    for (int ch = 0; ch < 4; ++ch) {
        const bool more = (ch < 3);
        if (more) {
            stageB_async(sBb + (buf ^ 1) * SB_BUF_BYTES, g_wb[wb2 + ch + 1], tid);
            cpasync_commit();
        }
        const uint32_t bB = sBb + buf * SB_BUF_BYTES;
        #pragma unroll
        for (int ks = 0; ks < 2; ++ks) {
            #pragma unroll
            for (int p = 0; p < 3; ++p) {
                const int ak = ch * 32 + ks * 16 + ((p == 1) ? 128 : 0);
                const int bk = ((p == 2) ? 32 : 0) + ks * 16;
                uint32_t a[2][4], b[2][4];
                #pragma unroll
                for (int mt = 0; mt < 2; ++mt)
                    ldsm_x4(a[mt], sUb + ((wr * 32 + mt * 16 + a_row_off) * 264 + ak + a_k_off) * 2);
                #pragma unroll
                for (int np = 0; np < 2; ++np)
                    ldsm_x4(b[np], bB + ((wc * 32 + np * 16 + b_n_off) * 72 + bk + b_k_off) * 2);
                #pragma unroll
                for (int np = 0; np < 2; ++np) {
                    mma_bf16(c[0][np * 2],     a[0], b[np][0], b[np][1]);
                    mma_bf16(c[1][np * 2],     a[1], b[np][0], b[np][1]);
                    mma_bf16(c[0][np * 2 + 1], a[0], b[np][2], b[np][3]);
                    mma_bf16(c[1][np * 2 + 1], a[1], b[np][2], b[np][3]);
                }
            }
        }
        cpasync_wait0();
        __syncthreads();
        buf ^= 1;
    }

    // ============ epilogue 2: bias2 -> global ============
    #pragma unroll
    for (int mt = 0; mt < 2; ++mt) {
        #pragma unroll
        for (int nt = 0; nt < 4; ++nt) {
            int col = wc * 32 + nt * 8 + tg * 2;
            float bx = bias2[col], by = bias2[col + 1];
            int r0 = brow + wr * 32 + mt * 16 + gid;
            float v0 = c[mt][nt][0] + bx, v1 = c[mt][nt][1] + by;
            float v2 = c[mt][nt][2] + bx, v3 = c[mt][nt][3] + by;
            if (r0 < M)     *(float2*)(Cout + (size_t)r0 * D + col)       = make_float2(v0, v1);
            if (r0 + 8 < M) *(float2*)(Cout + (size_t)(r0 + 8) * D + col) = make_float2(v2, v3);
        }
    }
}

// ---------------- final GEMM: C = concat(A0..A3) @ W + bias (pipelined) ----
__global__ void __launch_bounds__(256) k_gemm_final(
    const float* __restrict__ A0, const float* __restrict__ A1,
    const float* __restrict__ A2, const float* __restrict__ A3,
    int wbase, const float* __restrict__ bias, float* __restrict__ C, int M)
{
    extern __shared__ __align__(16) char dyn[];
    __nv_bfloat16* sA = (__nv_bfloat16*)dyn;                        // 2 x 128*72
    __nv_bfloat16* sB = (__nv_bfloat16*)(dyn + 2 * SB_BUF_BYTES);   // 2 x 128*72

    const int tid  = threadIdx.x;
    const int w    = tid >> 5;
    const int lane = tid & 31;
    const int wr   = w & 3;
    const int wc   = w >> 2;
    const int gid  = lane >> 2;
    const int tg   = lane & 3;
    const int lg   = lane >> 3;
    const int lr   = lane & 7;
    const int brow = blockIdx.x * 128;

    const uint32_t sAb = (uint32_t)__cvta_generic_to_shared(sA);
    const uint32_t sBb = (uint32_t)__cvta_generic_to_shared(sB);

    const int a_row_off = (lg & 1) * 8 + lr;
    const int a_k_off   = (lg >> 1) * 8;
    const int b_n_off   = (lg >> 1) * 8 + lr;
    const int b_k_off   = (lg & 1) * 8;

    const float* srcs[4] = {A0, A1, A2, A3};

    float c[2][8][4];
    #pragma unroll
    for (int mt = 0; mt < 2; ++mt)
        #pragma unroll
        for (int nt = 0; nt < 8; ++nt)
            #pragma unroll
            for (int j = 0; j < 4; ++j) c[mt][nt][j] = 0.f;

    const int arow = tid >> 1;          // 0..127
    const int aq   = (tid & 1) * 16;    // 16 fp32 each
    const int grow = brow + arow;

    float v[16];
    auto loadA = [&](int ch) {
        if (grow < M) {
            const float* ap = srcs[ch >> 2] + (size_t)grow * D + (ch & 3) * 32 + aq;
            #pragma unroll
            for (int i = 0; i < 4; ++i) {
                float4 f = *(const float4*)(ap + i * 4);
                v[i * 4 + 0] = f.x; v[i * 4 + 1] = f.y; v[i * 4 + 2] = f.z; v[i * 4 + 3] = f.w;
            }
        } else {
            #pragma unroll
            for (int i = 0; i < 16; ++i) v[i] = 0.f;
        }
    };
    auto storeA = [&](int b) {
        __nv_bfloat16* dst = sA + b * (SB_BUF_BYTES / 2);
        uint4 hiq, loq;
        pack8(v, hiq, loq);
        *(uint4*)&dst[arow * 72 + aq]      = hiq;
        *(uint4*)&dst[arow * 72 + 32 + aq] = loq;
        pack8(v + 8, hiq, loq);
        *(uint4*)&dst[arow * 72 + aq + 8]      = hiq;
        *(uint4*)&dst[arow * 72 + 32 + aq + 8] = loq;
    };

    // ---------- prologue ----------
    stageB_async(sBb, g_wb[wbase], tid);
    cpasync_commit();
    loadA(0);
    storeA(0);
    cpasync_wait0();
    __syncthreads();

    int buf = 0;
    for (int ch = 0; ch < 16; ++ch) {
        const bool more = (ch < 15);
        if (more) {
            stageB_async(sBb + (buf ^ 1) * SB_BUF_BYTES, g_wb[wbase + ch + 1], tid);
            cpasync_commit();
            loadA(ch + 1);
        }
        const uint32_t aB = sAb + buf * SB_BUF_BYTES;
        const uint32_t bB = sBb + buf * SB_BUF_BYTES;
        #pragma unroll
        for (int ks = 0; ks < 2; ++ks) {
            #pragma unroll
            for (int p = 0; p < 3; ++p) {
                const int ak = ((p == 1) ? 32 : 0) + ks * 16;
                const int bk = ((p == 2) ? 32 : 0) + ks * 16;
                uint32_t a[2][4], b[4][4];
                #pragma unroll
                for (int mt = 0; mt < 2; ++mt)
                    ldsm_x4(a[mt], aB + ((wr * 32 + mt * 16 + a_row_off) * 72 + ak + a_k_off) * 2);
                #pragma unroll
                for (int np = 0; np < 4; ++np)
                    ldsm_x4(b[np], bB + ((wc * 64 + np * 16 + b_n_off) * 72 + bk + b_k_off) * 2);
                #pragma unroll
                for (int np = 0; np < 4; ++np) {
                    mma_bf16(c[0][np * 2],     a[0], b[np][0], b[np][1]);
                    mma_bf16(c[1][np * 2],     a[1], b[np][0], b[np][1]);
                    mma_bf16(c[0][np * 2 + 1], a[0], b[np][2], b[np][3]);
                    mma_bf16(c[1][np * 2 + 1], a[1], b[np][2], b[np][3]);
                }
            }
        }
        if (more) storeA(buf ^ 1);
        cpasync_wait0();
        __syncthreads();
        buf ^= 1;
    }

    #pragma unroll
    for (int mt = 0; mt < 2; ++mt) {
        #pragma unroll
        for (int nt = 0; nt < 8; ++nt) {
            int col  = wc * 64 + nt * 8 + tg * 2;
            float bx = bias[col], by = bias[col + 1];
            int r0 = brow + wr * 32 + mt * 16 + gid;
            float v0 = c[mt][nt][0] + bx, v1 = c[mt][nt][1] + by;
            float v2 = c[mt][nt][2] + bx, v3 = c[mt][nt][3] + by;
            if (r0 < M)     *(float2*)(C + (size_t)r0 * D + col)       = make_float2(v0, v1);
            if (r0 + 8 < M) *(float2*)(C + (size_t)(r0 + 8) * D + col) = make_float2(v2, v3);
        }
    }
}

// ---------------- launcher ----------------
extern "C" void kernel_launch(void* const* d_in, const int* in_sizes, int n_in,
                              void* d_out, int out_size) {
    const float* x   = (const float*)d_in[0];
    const int*   ei  = (const int*)  d_in[1];
    const float* ea  = (const float*)d_in[2];
    const float* lw  = (const float*)d_in[3];
    const float* lb  = (const float*)d_in[4];
    const float* eps = (const float*)d_in[5];
    const float* w1  = (const float*)d_in[6];
    const float* b1  = (const float*)d_in[7];
    const float* w2  = (const float*)d_in[8];
    const float* b2  = (const float*)d_in[9];
    const float* fw  = (const float*)d_in[10];
    const float* fb  = (const float*)d_in[11];
    float* out = (float*)d_out;

    const int N = in_sizes[0] / D;
    const int E = in_sizes[2];

    const int MLP_SMEM   = SMID_BYTES + 2 * SB_BUF_BYTES;   // 70656
    const int FINAL_SMEM = 4 * SB_BUF_BYTES;                // 73728
    cudaFuncSetAttribute(k_layer_mlp,  cudaFuncAttributeMaxDynamicSharedMemorySize, MLP_SMEM);
    cudaFuncSetAttribute(k_gemm_final, cudaFuncAttributeMaxDynamicSharedMemorySize, FINAL_SMEM);

    float *hbuf, *tmp;
    cudaGetSymbolAddress((void**)&hbuf, g_h);
    cudaGetSymbolAddress((void**)&tmp,  g_tmp);

    // weight prep + CSR build
    k_wprep<<<(40 * 128 * 32 + 255) / 256, 256>>>(w1, w2, fw);
    k_zero<<<(N + 255) / 256, 256>>>(N);
    k_hist<<<(E + 255) / 256, 256>>>(ei + E, E);
    const int nb = (N + 1023) / 1024;
    k_scan1<<<nb, 1024>>>(N);
    k_scan2<<<1, 32>>>(nb);
    k_scan3<<<nb, 1024>>>(N);
    k_scatter<<<(E + 255) / 256, 256>>>(ei, ei + E, ea, E);

    const float* h = x;
    for (int l = 0; l < 3; ++l) {
        float* hl = hbuf + (size_t)l * NMAX * D;
        k_agg<<<(N + 7) / 8, 256>>>(h, lw + l * D, lb + l * D, eps, l, tmp, N);
        k_layer_mlp<<<(N + 63) / 64, 256, MLP_SMEM>>>(tmp, (l * 2 + 0) * 4, (l * 2 + 1) * 4,
                                                      b1 + l * D, b2 + l * D, hl, N);
        h = hl;
    }

    // final: [x | h1 | h2 | h3] @ fw + fb
    k_gemm_final<<<(N + 127) / 128, 256, FINAL_SMEM>>>(x, hbuf, hbuf + (size_t)NMAX * D,
                                                       hbuf + (size_t)2 * NMAX * D, 24, fb, out, N);
}